// round 6
// baseline (speedup 1.0000x reference)
#include <cuda_runtime.h>
#include <cuda_bf16.h>
#include <cstdint>

// Problem constants
#define BB 4
#define TT 2048
#define CC 1024
#define HH 16
#define DD 64
#define MM (BB*TT)        // 8192

// Scratch (device globals: allocation-free rule)
__device__ float g_qkv[(size_t)MM * 3 * CC];     // [8192, 3072]
__device__ float g_att[(size_t)MM * CC];         // [8192, 1024] (tf32)
__device__ float g_x32[(size_t)MM * CC];         // tf32-rounded x
__device__ float g_wqkvT[(size_t)3 * CC * CC];   // [3072, 1024] (w_qkv^T, tf32)
__device__ float g_woutT[(size_t)CC * CC];       // [1024, 1024] (w_out^T, tf32)

// ---------------------------------------------------------------------------
// Helpers
// ---------------------------------------------------------------------------
__device__ __forceinline__ uint32_t smem_u32(const void* p) {
    uint32_t a;
    asm("{ .reg .u64 t; cvta.to.shared.u64 t, %1; cvt.u32.u64 %0, t; }"
        : "=r"(a) : "l"(p));
    return a;
}

__device__ __forceinline__ float to_tf32(float x) {
    uint32_t u;
    asm("cvt.rna.tf32.f32 %0, %1;" : "=r"(u) : "f"(x));
    return __uint_as_float(u);
}

__device__ __forceinline__ float ex2(float x) {
    float y;
    asm("ex2.approx.ftz.f32 %0, %1;" : "=f"(y) : "f"(x));
    return y;
}

__device__ __forceinline__ void cp_async16(uint32_t dst, const void* src) {
    asm volatile("cp.async.cg.shared.global [%0], [%1], 16;\n"
                 :: "r"(dst), "l"(src));
}
__device__ __forceinline__ void cp_commit() {
    asm volatile("cp.async.commit_group;\n" ::: "memory");
}
__device__ __forceinline__ void cp_wait1() {
    asm volatile("cp.async.wait_group 1;\n" ::: "memory");
}
__device__ __forceinline__ void cp_wait0() {
    asm volatile("cp.async.wait_group 0;\n" ::: "memory");
}

// m16n8k8 tf32 mma, fp32 accumulate
__device__ __forceinline__ void mma_tf32(float* c, const float* a, const float* b) {
    asm volatile(
        "mma.sync.aligned.m16n8k8.row.col.f32.tf32.tf32.f32 "
        "{%0,%1,%2,%3}, {%4,%5,%6,%7}, {%8,%9}, {%0,%1,%2,%3};\n"
        : "+f"(c[0]), "+f"(c[1]), "+f"(c[2]), "+f"(c[3])
        : "r"(__float_as_uint(a[0])), "r"(__float_as_uint(a[1])),
          "r"(__float_as_uint(a[2])), "r"(__float_as_uint(a[3])),
          "r"(__float_as_uint(b[0])), "r"(__float_as_uint(b[1])));
}

__device__ __forceinline__ void mma_tf32b(float* c, const float* a,
                                          float b0, float b1) {
    asm volatile(
        "mma.sync.aligned.m16n8k8.row.col.f32.tf32.tf32.f32 "
        "{%0,%1,%2,%3}, {%4,%5,%6,%7}, {%8,%9}, {%0,%1,%2,%3};\n"
        : "+f"(c[0]), "+f"(c[1]), "+f"(c[2]), "+f"(c[3])
        : "r"(__float_as_uint(a[0])), "r"(__float_as_uint(a[1])),
          "r"(__float_as_uint(a[2])), "r"(__float_as_uint(a[3])),
          "r"(__float_as_uint(b0)), "r"(__float_as_uint(b1)));
}

// ---------------------------------------------------------------------------
// Elementwise tf32 round
// ---------------------------------------------------------------------------
__global__ void tf32_convert_kernel(const float* __restrict__ in,
                                    float* __restrict__ out, int n)
{
    int i = (blockIdx.x * blockDim.x + threadIdx.x) * 4;
    if (i < n) {
        float4 v = *(const float4*)(in + i);
        v.x = to_tf32(v.x); v.y = to_tf32(v.y);
        v.z = to_tf32(v.z); v.w = to_tf32(v.w);
        *(float4*)(out + i) = v;
    }
}

// ---------------------------------------------------------------------------
// Weight transpose with tf32 rounding
// ---------------------------------------------------------------------------
__global__ void transpose_kernel(const float* __restrict__ in,
                                 float* __restrict__ out, int R, int C_)
{
    __shared__ float tile[32][33];
    const int c0 = blockIdx.x * 32, r0 = blockIdx.y * 32;
    const int tx = threadIdx.x, ty = threadIdx.y;   // 32 x 8
    #pragma unroll
    for (int i = 0; i < 32; i += 8)
        tile[ty + i][tx] = in[(size_t)(r0 + ty + i) * C_ + c0 + tx];
    __syncthreads();
    #pragma unroll
    for (int i = 0; i < 32; i += 8)
        out[(size_t)(c0 + ty + i) * R + r0 + tx] = to_tf32(tile[tx][ty + i]);
}

// ---------------------------------------------------------------------------
// tf32 mma.sync GEMM: C = A @ Bt^T + bias.  3-stage cp.async pipeline,
// one barrier per K-iteration. A and B pre-rounded to tf32.
// ---------------------------------------------------------------------------
#define GBM 128
#define GBN 128
#define GBK 16
#define SPAD 20
#define GSTAGES 3
#define GEMM_SMEM (GSTAGES * 2 * GBM * SPAD * 4)

__global__ __launch_bounds__(256, 2)
void gemm_tf32_kernel(const float* __restrict__ A, const float* __restrict__ Bt,
                      const float* __restrict__ bias, float* __restrict__ C,
                      int M, int N, int K)
{
    extern __shared__ __align__(16) float gsm[];
    float (*As)[GBM][SPAD] = (float(*)[GBM][SPAD])gsm;
    float (*Bs)[GBM][SPAD] = (float(*)[GBM][SPAD])(gsm + GSTAGES * GBM * SPAD);

    const int tid  = threadIdx.x;
    const int wid  = tid >> 5;
    const int lane = tid & 31;
    const int gid  = lane >> 2;
    const int tig  = lane & 3;

    const int warp_m = wid & 1;
    const int warp_n = wid >> 1;

    const int brow = blockIdx.y, bcol = blockIdx.x;
    const float* Abase = A  + (size_t)brow * GBM * K;
    const float* Bbase = Bt + (size_t)bcol * GBN * K;

    float acc[4][4][4];
    #pragma unroll
    for (int i = 0; i < 4; i++)
        #pragma unroll
        for (int j = 0; j < 4; j++)
            #pragma unroll
            for (int r = 0; r < 4; r++) acc[i][j][r] = 0.0f;

    const uint32_t sA0 = smem_u32(&As[0][0][0]);
    const uint32_t sB0 = smem_u32(&Bs[0][0][0]);
    const uint32_t stageBytes = GBM * SPAD * 4;

    auto load_tile = [&](int it) {
        const int stage = it % GSTAGES;
        const int koff = it * GBK;
        #pragma unroll
        for (int q = 0; q < 2; q++) {
            const int idx = q * 256 + tid;
            const int row = idx >> 2;
            const int c4  = (idx & 3) * 4;
            const uint32_t doff = stage * stageBytes + (row * SPAD + c4) * 4;
            cp_async16(sA0 + doff, Abase + (size_t)row * K + koff + c4);
            cp_async16(sB0 + doff, Bbase + (size_t)row * K + koff + c4);
        }
        cp_commit();
    };

    const int nit = K / GBK;
    load_tile(0);
    load_tile(1);

    for (int it = 0; it < nit; ++it) {
        if (it == nit - 1) cp_wait0(); else cp_wait1();
        __syncthreads();
        if (it + 2 < nit) load_tile(it + 2);

        const int st = it % GSTAGES;
        #pragma unroll
        for (int kk = 0; kk < GBK; kk += 8) {
            float a[4][4], b[4][2];
            #pragma unroll
            for (int i = 0; i < 4; i++) {
                const int r = warp_m * 64 + i * 16 + gid;
                a[i][0] = As[st][r][kk + tig];
                a[i][1] = As[st][r + 8][kk + tig];
                a[i][2] = As[st][r][kk + tig + 4];
                a[i][3] = As[st][r + 8][kk + tig + 4];
            }
            #pragma unroll
            for (int j = 0; j < 4; j++) {
                const int r = warp_n * 32 + j * 8 + gid;
                b[j][0] = Bs[st][r][kk + tig];
                b[j][1] = Bs[st][r][kk + tig + 4];
            }
            #pragma unroll
            for (int i = 0; i < 4; i++)
                #pragma unroll
                for (int j = 0; j < 4; j++)
                    mma_tf32(acc[i][j], a[i], b[j]);
        }
    }

    #pragma unroll
    for (int i = 0; i < 4; i++) {
        const int row0 = brow * GBM + warp_m * 64 + i * 16 + gid;
        #pragma unroll
        for (int j = 0; j < 4; j++) {
            const int col = bcol * GBN + warp_n * 32 + j * 8 + 2 * tig;
            const float bx = bias[col], by = bias[col + 1];
            float2 v0 = make_float2(acc[i][j][0] + bx, acc[i][j][1] + by);
            float2 v1 = make_float2(acc[i][j][2] + bx, acc[i][j][3] + by);
            *(float2*)(C + (size_t)row0 * N + col) = v0;
            *(float2*)(C + (size_t)(row0 + 8) * N + col) = v1;
        }
    }
}

// ---------------------------------------------------------------------------
// Flash attention with tf32 mma.sync.
// CTA: 256 q rows x one (b,h); 16 warps x 16 rows; kv tiles of 64.
// Each K/V smem tile now amortizes over 256 q rows (half the LDS per mma).
// S = Q @ (Khi + Klo)^T (K error-compensated); P stays in registers (shuffle).
// ---------------------------------------------------------------------------
#define APAD 68
#define AQROWS 256
#define ATHREADS 512

__global__ __launch_bounds__(ATHREADS, 1)
void attn_mma_kernel(const float* __restrict__ qkv, float* __restrict__ out)
{
    extern __shared__ __align__(16) float dsm[];
    constexpr int OFF_KH = 0;                 // 64 x 68
    constexpr int OFF_KL = 64 * APAD;         // 64 x 68
    constexpr int OFF_VT = 2 * 64 * APAD;     // 64 x 68 (d-major)
    // Q staged at offset 0 (256 x 68 = 17408 floats, whole buffer)

    const int qb = (int)gridDim.x - 1 - (int)blockIdx.x;  // heavy tiles first
    const int h  = blockIdx.y;
    const int b  = blockIdx.z;
    const int q0 = qb * AQROWS;

    const int tid  = threadIdx.x;
    const int w    = tid >> 5;
    const int lane = tid & 31;
    const int gid  = lane >> 2;
    const int tig  = lane & 3;

    // Stage Q (exp2-domain prescale, tf32)
    const float SC = 0.125f * 1.4426950408889634f;
    {
        const float* qb_ptr = qkv + ((size_t)(b * TT + q0)) * (3 * CC) + h * DD;
        for (int idx = tid; idx < AQROWS * 16; idx += ATHREADS) {
            const int row = idx >> 4, c4 = (idx & 15) << 2;
            float4 v = *(const float4*)(qb_ptr + (size_t)row * (3 * CC) + c4);
            float* d = &dsm[row * APAD + c4];
            d[0] = to_tf32(v.x * SC);
            d[1] = to_tf32(v.y * SC);
            d[2] = to_tf32(v.z * SC);
            d[3] = to_tf32(v.w * SC);
        }
    }
    __syncthreads();

    const int r0l = w * 16 + gid;      // local q row
    const int r0g = q0 + r0l;          // global q row

    float qf[8][4];
    #pragma unroll
    for (int ks = 0; ks < 8; ks++) {
        const int kb = ks * 8 + tig;
        qf[ks][0] = dsm[r0l * APAD + kb];
        qf[ks][1] = dsm[(r0l + 8) * APAD + kb];
        qf[ks][2] = dsm[r0l * APAD + kb + 4];
        qf[ks][3] = dsm[(r0l + 8) * APAD + kb + 4];
    }
    __syncthreads();   // Q region about to be overwritten by K/V

    float O[8][4];
    #pragma unroll
    for (int j = 0; j < 8; j++)
        #pragma unroll
        for (int r = 0; r < 4; r++) O[j][r] = 0.0f;
    float m0 = -1e30f, m1 = -1e30f, l0 = 0.0f, l1 = 0.0f;

    const int src0 = (lane & 28) | (tig >> 1);
    const int src1 = src0 + 2;
    const bool oddt = (tig & 1);

    const int ntiles = 4 * (qb + 1);

    for (int t = 0; t < ntiles; t++) {
        const int kv0 = t * 64;

        // Load K (hi/lo split) and V (transposed), tf32-rounded
        for (int idx = tid; idx < 64 * 16; idx += ATHREADS) {
            const int row = idx >> 4, c4 = (idx & 15) << 2;
            const float* kp = qkv + ((size_t)(b * TT + kv0 + row)) * (3 * CC)
                              + CC + h * DD + c4;
            float4 k4 = *(const float4*)kp;
            float4 v4 = *(const float4*)(kp + CC);
            float* kh = &dsm[OFF_KH + row * APAD + c4];
            float* kl = &dsm[OFF_KL + row * APAD + c4];
            float hx = to_tf32(k4.x); kh[0] = hx; kl[0] = to_tf32(k4.x - hx);
            float hy = to_tf32(k4.y); kh[1] = hy; kl[1] = to_tf32(k4.y - hy);
            float hz = to_tf32(k4.z); kh[2] = hz; kl[2] = to_tf32(k4.z - hz);
            float hw = to_tf32(k4.w); kh[3] = hw; kl[3] = to_tf32(k4.w - hw);
            dsm[OFF_VT + (c4 + 0) * APAD + row] = to_tf32(v4.x);
            dsm[OFF_VT + (c4 + 1) * APAD + row] = to_tf32(v4.y);
            dsm[OFF_VT + (c4 + 2) * APAD + row] = to_tf32(v4.z);
            dsm[OFF_VT + (c4 + 3) * APAD + row] = to_tf32(v4.w);
        }
        __syncthreads();

        // S = Q @ K^T  (hi + lo)
        float s[8][4];
        #pragma unroll
        for (int j = 0; j < 8; j++)
            #pragma unroll
            for (int r = 0; r < 4; r++) s[j][r] = 0.0f;

        #pragma unroll
        for (int ks = 0; ks < 8; ks++) {
            const int kb = ks * 8 + tig;
            #pragma unroll
            for (int j = 0; j < 8; j++) {
                const int rb = (j * 8 + gid) * APAD + kb;
                mma_tf32b(s[j], qf[ks], dsm[OFF_KH + rb], dsm[OFF_KH + rb + 4]);
                mma_tf32b(s[j], qf[ks], dsm[OFF_KL + rb], dsm[OFF_KL + rb + 4]);
            }
        }

        // Causal mask on diagonal-straddling tiles (last 4 of this CTA)
        if (t + 4 >= ntiles) {
            #pragma unroll
            for (int j = 0; j < 8; j++) {
                const int col = kv0 + j * 8 + 2 * tig;
                if (col     > r0g)     s[j][0] = -1e30f;
                if (col + 1 > r0g)     s[j][1] = -1e30f;
                if (col     > r0g + 8) s[j][2] = -1e30f;
                if (col + 1 > r0g + 8) s[j][3] = -1e30f;
            }
        }

        // Online softmax (exp2 domain)
        float mt0 = s[0][0], mt1 = s[0][2];
        #pragma unroll
        for (int j = 0; j < 8; j++) {
            mt0 = fmaxf(mt0, fmaxf(s[j][0], s[j][1]));
            mt1 = fmaxf(mt1, fmaxf(s[j][2], s[j][3]));
        }
        mt0 = fmaxf(mt0, __shfl_xor_sync(0xffffffffu, mt0, 1));
        mt0 = fmaxf(mt0, __shfl_xor_sync(0xffffffffu, mt0, 2));
        mt1 = fmaxf(mt1, __shfl_xor_sync(0xffffffffu, mt1, 1));
        mt1 = fmaxf(mt1, __shfl_xor_sync(0xffffffffu, mt1, 2));

        const float mn0 = fmaxf(m0, mt0), mn1 = fmaxf(m1, mt1);
        const float c0 = ex2(m0 - mn0), c1 = ex2(m1 - mn1);
        l0 *= c0; l1 *= c1;
        #pragma unroll
        for (int j = 0; j < 8; j++) {
            O[j][0] *= c0; O[j][1] *= c0;
            O[j][2] *= c1; O[j][3] *= c1;
        }
        m0 = mn0; m1 = mn1;

        // Fused: exponentiate, shuffle P into A-fragments, PV mma
        #pragma unroll
        for (int j = 0; j < 8; j++) {
            float p0 = ex2(s[j][0] - mn0), p1 = ex2(s[j][1] - mn0);
            float p2 = ex2(s[j][2] - mn1), p3 = ex2(s[j][3] - mn1);
            l0 += p0 + p1;
            l1 += p2 + p3;
            p0 = to_tf32(p0); p1 = to_tf32(p1);
            p2 = to_tf32(p2); p3 = to_tf32(p3);

            float u0 = __shfl_sync(0xffffffffu, p0, src0);
            float u1 = __shfl_sync(0xffffffffu, p1, src0);
            float u2 = __shfl_sync(0xffffffffu, p2, src0);
            float u3 = __shfl_sync(0xffffffffu, p3, src0);
            float v0 = __shfl_sync(0xffffffffu, p0, src1);
            float v1 = __shfl_sync(0xffffffffu, p1, src1);
            float v2 = __shfl_sync(0xffffffffu, p2, src1);
            float v3 = __shfl_sync(0xffffffffu, p3, src1);

            float a[4];
            a[0] = oddt ? u1 : u0;
            a[1] = oddt ? u3 : u2;
            a[2] = oddt ? v1 : v0;
            a[3] = oddt ? v3 : v2;

            const int kb = j * 8 + tig;
            #pragma unroll
            for (int jo = 0; jo < 8; jo++) {
                const int vb = OFF_VT + (jo * 8 + gid) * APAD + kb;
                mma_tf32b(O[jo], a, dsm[vb], dsm[vb + 4]);
            }
        }
        __syncthreads();
    }

    // Finalize (tf32-round output: it feeds the out-proj GEMM A operand)
    l0 += __shfl_xor_sync(0xffffffffu, l0, 1);
    l0 += __shfl_xor_sync(0xffffffffu, l0, 2);
    l1 += __shfl_xor_sync(0xffffffffu, l1, 1);
    l1 += __shfl_xor_sync(0xffffffffu, l1, 2);
    const float i0 = 1.0f / l0, i1 = 1.0f / l1;

    float* ob = out + ((size_t)(b * TT + r0g)) * CC + h * DD;
    #pragma unroll
    for (int j = 0; j < 8; j++) {
        const int cb = j * 8 + 2 * tig;
        *(float2*)(ob + cb) =
            make_float2(to_tf32(O[j][0] * i0), to_tf32(O[j][1] * i0));
        *(float2*)(ob + (size_t)8 * CC + cb) =
            make_float2(to_tf32(O[j][2] * i1), to_tf32(O[j][3] * i1));
    }
}

#define ATTN_SMEM (AQROWS * APAD * 4)   // 69,632 B (Q stage; K/V reuse subset)

// ---------------------------------------------------------------------------
// Launch
// ---------------------------------------------------------------------------
extern "C" void kernel_launch(void* const* d_in, const int* in_sizes, int n_in,
                              void* d_out, int out_size)
{
    const float* x     = (const float*)d_in[0];
    const float* w_qkv = (const float*)d_in[1];
    const float* b_qkv = (const float*)d_in[2];
    const float* w_out = (const float*)d_in[3];
    const float* b_out = (const float*)d_in[4];
    float* out = (float*)d_out;

    float* qkv = nullptr;   cudaGetSymbolAddress((void**)&qkv, g_qkv);
    float* att = nullptr;   cudaGetSymbolAddress((void**)&att, g_att);
    float* x32 = nullptr;   cudaGetSymbolAddress((void**)&x32, g_x32);
    float* wqkvT = nullptr; cudaGetSymbolAddress((void**)&wqkvT, g_wqkvT);
    float* woutT = nullptr; cudaGetSymbolAddress((void**)&woutT, g_woutT);

    cudaFuncSetAttribute(gemm_tf32_kernel,
                         cudaFuncAttributeMaxDynamicSharedMemorySize, GEMM_SMEM);
    cudaFuncSetAttribute(attn_mma_kernel,
                         cudaFuncAttributeMaxDynamicSharedMemorySize, ATTN_SMEM);

    // Pre-round x; transpose+round weights
    {
        const int n = MM * CC;
        tf32_convert_kernel<<<n / (256 * 4), 256>>>(x, x32, n);
        dim3 blk(32, 8);
        transpose_kernel<<<dim3((3 * CC) / 32, CC / 32), blk>>>(w_qkv, wqkvT, CC, 3 * CC);
        transpose_kernel<<<dim3(CC / 32, CC / 32), blk>>>(w_out, woutT, CC, CC);
    }

    // QKV projection
    {
        dim3 grid((3 * CC) / GBN, MM / GBM);
        gemm_tf32_kernel<<<grid, 256, GEMM_SMEM>>>(x32, wqkvT, b_qkv, qkv, MM, 3 * CC, CC);
    }

    // Flash attention (tf32 mma, 256-row CTAs)
    {
        dim3 grid(TT / AQROWS, HH, BB);
        attn_mma_kernel<<<grid, ATHREADS, ATTN_SMEM>>>(qkv, att);
    }

    // Output projection
    {
        dim3 grid(CC / GBN, MM / GBM);
        gemm_tf32_kernel<<<grid, 256, GEMM_SMEM>>>(att, woutT, b_out, out, MM, CC, CC);
    }
}

// round 8
// speedup vs baseline: 1.6546x; 1.6546x over previous
#include <cuda_runtime.h>
#include <cuda_bf16.h>
#include <cstdint>

// Problem constants
#define BB 4
#define TT 2048
#define CC 1024
#define HH 16
#define DD 64
#define MM (BB*TT)        // 8192

// Scratch (device globals: allocation-free rule)
__device__ float g_qkv[(size_t)MM * 3 * CC];     // [8192, 3072]
__device__ float g_att[(size_t)MM * CC];         // [8192, 1024] (tf32)
__device__ float g_x32[(size_t)MM * CC];         // tf32-rounded x
__device__ float g_wqkvT[(size_t)3 * CC * CC];   // [3072, 1024] (w_qkv^T, tf32)
__device__ float g_woutT[(size_t)CC * CC];       // [1024, 1024] (w_out^T, tf32)

// ---------------------------------------------------------------------------
// Helpers
// ---------------------------------------------------------------------------
__device__ __forceinline__ float to_tf32(float x) {
    uint32_t u;
    asm("cvt.rna.tf32.f32 %0, %1;" : "=r"(u) : "f"(x));
    return __uint_as_float(u);
}

__device__ __forceinline__ float ex2(float x) {
    float y;
    asm("ex2.approx.ftz.f32 %0, %1;" : "=f"(y) : "f"(x));
    return y;
}

// pack two f32 -> bf16x2 (x in low half, y in high half)
__device__ __forceinline__ uint32_t pack_bf16x2(float x, float y) {
    uint32_t r;
    asm("cvt.rn.bf16x2.f32 %0, %1, %2;" : "=r"(r) : "f"(y), "f"(x));
    return r;
}

// split float pair into bf16x2 hi + bf16x2 residual
__device__ __forceinline__ void split_bf16(float x, float y,
                                           uint32_t& hi, uint32_t& lo) {
    __nv_bfloat16 hx = __float2bfloat16_rn(x);
    __nv_bfloat16 hy = __float2bfloat16_rn(y);
    float rx = x - __bfloat162float(hx);
    float ry = y - __bfloat162float(hy);
    hi = pack_bf16x2(__bfloat162float(hx), __bfloat162float(hy));
    lo = pack_bf16x2(rx, ry);
}

// m16n8k8 tf32 mma, fp32 accumulate
__device__ __forceinline__ void mma_tf32(float* c, const float* a, const float* b) {
    asm volatile(
        "mma.sync.aligned.m16n8k8.row.col.f32.tf32.tf32.f32 "
        "{%0,%1,%2,%3}, {%4,%5,%6,%7}, {%8,%9}, {%0,%1,%2,%3};\n"
        : "+f"(c[0]), "+f"(c[1]), "+f"(c[2]), "+f"(c[3])
        : "r"(__float_as_uint(a[0])), "r"(__float_as_uint(a[1])),
          "r"(__float_as_uint(a[2])), "r"(__float_as_uint(a[3])),
          "r"(__float_as_uint(b[0])), "r"(__float_as_uint(b[1])));
}

__device__ __forceinline__ void mma_tf32b(float* c, const float* a,
                                          float b0, float b1) {
    asm volatile(
        "mma.sync.aligned.m16n8k8.row.col.f32.tf32.tf32.f32 "
        "{%0,%1,%2,%3}, {%4,%5,%6,%7}, {%8,%9}, {%0,%1,%2,%3};\n"
        : "+f"(c[0]), "+f"(c[1]), "+f"(c[2]), "+f"(c[3])
        : "r"(__float_as_uint(a[0])), "r"(__float_as_uint(a[1])),
          "r"(__float_as_uint(a[2])), "r"(__float_as_uint(a[3])),
          "r"(__float_as_uint(b0)), "r"(__float_as_uint(b1)));
}

// m16n8k16 bf16 mma, fp32 accumulate
__device__ __forceinline__ void mma_bf16(float* c, const uint32_t* a,
                                         uint32_t b0, uint32_t b1) {
    asm volatile(
        "mma.sync.aligned.m16n8k16.row.col.f32.bf16.bf16.f32 "
        "{%0,%1,%2,%3}, {%4,%5,%6,%7}, {%8,%9}, {%0,%1,%2,%3};\n"
        : "+f"(c[0]), "+f"(c[1]), "+f"(c[2]), "+f"(c[3])
        : "r"(a[0]), "r"(a[1]), "r"(a[2]), "r"(a[3]),
          "r"(b0), "r"(b1));
}

// ---------------------------------------------------------------------------
// Elementwise tf32 round
// ---------------------------------------------------------------------------
__global__ void tf32_convert_kernel(const float* __restrict__ in,
                                    float* __restrict__ out, int n)
{
    int i = (blockIdx.x * blockDim.x + threadIdx.x) * 4;
    if (i < n) {
        float4 v = *(const float4*)(in + i);
        v.x = to_tf32(v.x); v.y = to_tf32(v.y);
        v.z = to_tf32(v.z); v.w = to_tf32(v.w);
        *(float4*)(out + i) = v;
    }
}

// ---------------------------------------------------------------------------
// Weight transpose with tf32 rounding
// ---------------------------------------------------------------------------
__global__ void transpose_kernel(const float* __restrict__ in,
                                 float* __restrict__ out, int R, int C_)
{
    __shared__ float tile[32][33];
    const int c0 = blockIdx.x * 32, r0 = blockIdx.y * 32;
    const int tx = threadIdx.x, ty = threadIdx.y;   // 32 x 8
    #pragma unroll
    for (int i = 0; i < 32; i += 8)
        tile[ty + i][tx] = in[(size_t)(r0 + ty + i) * C_ + c0 + tx];
    __syncthreads();
    #pragma unroll
    for (int i = 0; i < 32; i += 8)
        out[(size_t)(c0 + ty + i) * R + r0 + tx] = to_tf32(tile[tx][ty + i]);
}

// ---------------------------------------------------------------------------
// tf32 mma.sync GEMM (round-3 version, measured 383us): C = A @ Bt^T + bias
// ---------------------------------------------------------------------------
#define GBM 128
#define GBN 128
#define GBK 16
#define SPAD 20

__device__ __forceinline__ void cp_async16(uint32_t dst, const void* src) {
    asm volatile("cp.async.cg.shared.global [%0], [%1], 16;\n"
                 :: "r"(dst), "l"(src));
}
__device__ __forceinline__ void cp_commit() {
    asm volatile("cp.async.commit_group;\n" ::: "memory");
}
__device__ __forceinline__ void cp_wait1() {
    asm volatile("cp.async.wait_group 1;\n" ::: "memory");
}
__device__ __forceinline__ void cp_wait0() {
    asm volatile("cp.async.wait_group 0;\n" ::: "memory");
}

__device__ __forceinline__ uint32_t smem_u32(const void* p) {
    uint32_t a;
    asm("{ .reg .u64 t; cvta.to.shared.u64 t, %1; cvt.u32.u64 %0, t; }"
        : "=r"(a) : "l"(p));
    return a;
}

__global__ __launch_bounds__(256, 2)
void gemm_tf32_kernel(const float* __restrict__ A, const float* __restrict__ Bt,
                      const float* __restrict__ bias, float* __restrict__ C,
                      int M, int N, int K)
{
    __shared__ __align__(16) float As[2][GBM][SPAD];
    __shared__ __align__(16) float Bs[2][GBN][SPAD];

    const int tid  = threadIdx.x;
    const int wid  = tid >> 5;
    const int lane = tid & 31;
    const int gid  = lane >> 2;
    const int tig  = lane & 3;

    const int warp_m = wid & 1;
    const int warp_n = wid >> 1;

    const int brow = blockIdx.y, bcol = blockIdx.x;
    const float* Abase = A  + (size_t)brow * GBM * K;
    const float* Bbase = Bt + (size_t)bcol * GBN * K;

    float acc[4][4][4];
    #pragma unroll
    for (int i = 0; i < 4; i++)
        #pragma unroll
        for (int j = 0; j < 4; j++)
            #pragma unroll
            for (int r = 0; r < 4; r++) acc[i][j][r] = 0.0f;

    const uint32_t sA0 = smem_u32(&As[0][0][0]);
    const uint32_t sB0 = smem_u32(&Bs[0][0][0]);
    const uint32_t stageBytes = GBM * SPAD * 4;

    auto load_tile = [&](int it, int stage) {
        const int koff = it * GBK;
        #pragma unroll
        for (int q = 0; q < 2; q++) {
            const int idx = q * 256 + tid;
            const int row = idx >> 2;
            const int c4  = (idx & 3) * 4;
            const uint32_t doff = stage * stageBytes + (row * SPAD + c4) * 4;
            cp_async16(sA0 + doff, Abase + (size_t)row * K + koff + c4);
            cp_async16(sB0 + doff, Bbase + (size_t)row * K + koff + c4);
        }
    };

    const int nit = K / GBK;
    load_tile(0, 0);
    cp_commit();

    for (int it = 0; it < nit; ++it) {
        if (it + 1 < nit) {
            load_tile(it + 1, (it + 1) & 1);
            cp_commit();
            cp_wait1();
        } else {
            cp_wait0();
        }
        __syncthreads();

        const int st = it & 1;
        #pragma unroll
        for (int kk = 0; kk < GBK; kk += 8) {
            float a[4][4], b[4][2];
            #pragma unroll
            for (int i = 0; i < 4; i++) {
                const int r = warp_m * 64 + i * 16 + gid;
                a[i][0] = As[st][r][kk + tig];
                a[i][1] = As[st][r + 8][kk + tig];
                a[i][2] = As[st][r][kk + tig + 4];
                a[i][3] = As[st][r + 8][kk + tig + 4];
            }
            #pragma unroll
            for (int j = 0; j < 4; j++) {
                const int r = warp_n * 32 + j * 8 + gid;
                b[j][0] = Bs[st][r][kk + tig];
                b[j][1] = Bs[st][r][kk + tig + 4];
            }
            #pragma unroll
            for (int i = 0; i < 4; i++)
                #pragma unroll
                for (int j = 0; j < 4; j++)
                    mma_tf32(acc[i][j], a[i], b[j]);
        }
        __syncthreads();
    }

    #pragma unroll
    for (int i = 0; i < 4; i++) {
        const int row0 = brow * GBM + warp_m * 64 + i * 16 + gid;
        #pragma unroll
        for (int j = 0; j < 4; j++) {
            const int col = bcol * GBN + warp_n * 32 + j * 8 + 2 * tig;
            const float bx = bias[col], by = bias[col + 1];
            float2 v0 = make_float2(acc[i][j][0] + bx, acc[i][j][1] + by);
            float2 v1 = make_float2(acc[i][j][2] + bx, acc[i][j][3] + by);
            *(float2*)(C + (size_t)row0 * N + col) = v0;
            *(float2*)(C + (size_t)(row0 + 8) * N + col) = v1;
        }
    }
}

// ---------------------------------------------------------------------------
// Flash attention: bf16 3-term S + tf32 shuffle PV (hybrid).
// CTA: 128 q rows x one (b,h); 8 warps x 16 rows; kv tiles of 64.
// S = qhi*khi + qhi*klo + qlo*khi  (bf16 hi/lo; ~2^-16 effective on scores)
// PV = tf32 mma, P tf32-rounded and shuffled into A-fragments (round-5 path,
//      validated at rel_err 6.29e-4). V transposed tf32 in smem.
// ---------------------------------------------------------------------------
#define APAD 68       // f32 pitch for Q staging and VT
#define KPITCH 36     // u32 pitch for KH/KL (bank index 4*gid+tig = lane)
#define ASM_FLOATS (2 * 64 * KPITCH + 64 * APAD)   // 8960 floats = 35,840 B

__global__ __launch_bounds__(256, 2)
void attn_hyb_kernel(const float* __restrict__ qkv, float* __restrict__ out)
{
    __shared__ __align__(16) float dsm[ASM_FLOATS];
    uint32_t* KH = (uint32_t*)dsm;              // 64 x 36 u32
    uint32_t* KL = KH + 64 * KPITCH;            // 64 x 36 u32
    float*    VT = dsm + 2 * 64 * KPITCH;       // 64 x 68 f32 (d-major, tf32)

    const int qb = (int)gridDim.x - 1 - (int)blockIdx.x;  // heavy tiles first
    const int h  = blockIdx.y;
    const int b  = blockIdx.z;
    const int q0 = qb * 128;

    const int tid  = threadIdx.x;
    const int w    = tid >> 5;
    const int lane = tid & 31;
    const int gid  = lane >> 2;
    const int tig  = lane & 3;

    // Stage Q (scaled into exp2 domain, f32) in dsm[0 .. 128*68)
    const float SC = 0.125f * 1.4426950408889634f;
    {
        const float* qb_ptr = qkv + ((size_t)(b * TT + q0)) * (3 * CC) + h * DD;
        for (int idx = tid; idx < 128 * 16; idx += 256) {
            const int row = idx >> 4, c4 = (idx & 15) << 2;
            float4 v = *(const float4*)(qb_ptr + (size_t)row * (3 * CC) + c4);
            float* d = &dsm[row * APAD + c4];
            d[0] = v.x * SC; d[1] = v.y * SC;
            d[2] = v.z * SC; d[3] = v.w * SC;
        }
    }
    __syncthreads();

    const int r0l = w * 16 + gid;
    const int r0g = q0 + r0l;

    // Q hi/lo bf16 A-fragments: 4 k16-steps x 4 regs
    uint32_t qhi[4][4], qlo[4][4];
    #pragma unroll
    for (int ks = 0; ks < 4; ks++) {
        const int d0 = ks * 16 + 2 * tig;
        float2 x0 = *(float2*)&dsm[r0l * APAD + d0];
        float2 x1 = *(float2*)&dsm[(r0l + 8) * APAD + d0];
        float2 x2 = *(float2*)&dsm[r0l * APAD + d0 + 8];
        float2 x3 = *(float2*)&dsm[(r0l + 8) * APAD + d0 + 8];
        split_bf16(x0.x, x0.y, qhi[ks][0], qlo[ks][0]);
        split_bf16(x1.x, x1.y, qhi[ks][1], qlo[ks][1]);
        split_bf16(x2.x, x2.y, qhi[ks][2], qlo[ks][2]);
        split_bf16(x3.x, x3.y, qhi[ks][3], qlo[ks][3]);
    }
    __syncthreads();   // Q staging about to be overwritten by K/V

    float O[8][4];
    #pragma unroll
    for (int j = 0; j < 8; j++)
        #pragma unroll
        for (int r = 0; r < 4; r++) O[j][r] = 0.0f;
    float m0 = -1e30f, m1 = -1e30f, l0 = 0.0f, l1 = 0.0f;

    const int src0 = (lane & 28) | (tig >> 1);
    const int src1 = src0 + 2;
    const bool oddt = (tig & 1);

    const int ntiles = 2 * (qb + 1);

    for (int t = 0; t < ntiles; t++) {
        const int kv0 = t * 64;

        // Load K (hi/lo bf16) and V (transposed tf32)
        for (int idx = tid; idx < 64 * 16; idx += 256) {
            const int row = idx >> 4, c4 = (idx & 15) << 2;
            const float* kp = qkv + ((size_t)(b * TT + kv0 + row)) * (3 * CC)
                              + CC + h * DD + c4;
            float4 k4 = *(const float4*)kp;
            float4 v4 = *(const float4*)(kp + CC);
            uint32_t h0, L0, h1, L1;
            split_bf16(k4.x, k4.y, h0, L0);
            split_bf16(k4.z, k4.w, h1, L1);
            const int wi = row * KPITCH + (c4 >> 1);
            KH[wi] = h0; KH[wi + 1] = h1;
            KL[wi] = L0; KL[wi + 1] = L1;
            VT[(c4 + 0) * APAD + row] = to_tf32(v4.x);
            VT[(c4 + 1) * APAD + row] = to_tf32(v4.y);
            VT[(c4 + 2) * APAD + row] = to_tf32(v4.z);
            VT[(c4 + 3) * APAD + row] = to_tf32(v4.w);
        }
        __syncthreads();

        // S = Q @ K^T (bf16 3-term)
        float s[8][4];
        #pragma unroll
        for (int j = 0; j < 8; j++)
            #pragma unroll
            for (int r = 0; r < 4; r++) s[j][r] = 0.0f;

        #pragma unroll
        for (int ks = 0; ks < 4; ks++) {
            const int kb = ks * 8 + tig;
            #pragma unroll
            for (int j = 0; j < 8; j++) {
                const int base = (j * 8 + gid) * KPITCH + kb;
                const uint32_t bh0 = KH[base], bh1 = KH[base + 4];
                const uint32_t bl0 = KL[base], bl1 = KL[base + 4];
                mma_bf16(s[j], qhi[ks], bh0, bh1);
                mma_bf16(s[j], qhi[ks], bl0, bl1);
                mma_bf16(s[j], qlo[ks], bh0, bh1);
            }
        }

        // Causal mask on the two diagonal-straddling tiles
        if (t + 2 >= ntiles) {
            #pragma unroll
            for (int j = 0; j < 8; j++) {
                const int col = kv0 + j * 8 + 2 * tig;
                if (col     > r0g)     s[j][0] = -1e30f;
                if (col + 1 > r0g)     s[j][1] = -1e30f;
                if (col     > r0g + 8) s[j][2] = -1e30f;
                if (col + 1 > r0g + 8) s[j][3] = -1e30f;
            }
        }

        // Online softmax (exp2 domain)
        float mt0 = s[0][0], mt1 = s[0][2];
        #pragma unroll
        for (int j = 0; j < 8; j++) {
            mt0 = fmaxf(mt0, fmaxf(s[j][0], s[j][1]));
            mt1 = fmaxf(mt1, fmaxf(s[j][2], s[j][3]));
        }
        mt0 = fmaxf(mt0, __shfl_xor_sync(0xffffffffu, mt0, 1));
        mt0 = fmaxf(mt0, __shfl_xor_sync(0xffffffffu, mt0, 2));
        mt1 = fmaxf(mt1, __shfl_xor_sync(0xffffffffu, mt1, 1));
        mt1 = fmaxf(mt1, __shfl_xor_sync(0xffffffffu, mt1, 2));

        const float mn0 = fmaxf(m0, mt0), mn1 = fmaxf(m1, mt1);
        const float c0 = ex2(m0 - mn0), c1 = ex2(m1 - mn1);
        l0 *= c0; l1 *= c1;
        #pragma unroll
        for (int j = 0; j < 8; j++) {
            O[j][0] *= c0; O[j][1] *= c0;
            O[j][2] *= c1; O[j][3] *= c1;
        }
        m0 = mn0; m1 = mn1;

        // Fused: exponentiate, shuffle P into tf32 A-fragments, PV mma
        #pragma unroll
        for (int j = 0; j < 8; j++) {
            float p0 = ex2(s[j][0] - mn0), p1 = ex2(s[j][1] - mn0);
            float p2 = ex2(s[j][2] - mn1), p3 = ex2(s[j][3] - mn1);
            l0 += p0 + p1;
            l1 += p2 + p3;
            p0 = to_tf32(p0); p1 = to_tf32(p1);
            p2 = to_tf32(p2); p3 = to_tf32(p3);

            float u0 = __shfl_sync(0xffffffffu, p0, src0);
            float u1 = __shfl_sync(0xffffffffu, p1, src0);
            float u2 = __shfl_sync(0xffffffffu, p2, src0);
            float u3 = __shfl_sync(0xffffffffu, p3, src0);
            float v0 = __shfl_sync(0xffffffffu, p0, src1);
            float v1 = __shfl_sync(0xffffffffu, p1, src1);
            float v2 = __shfl_sync(0xffffffffu, p2, src1);
            float v3 = __shfl_sync(0xffffffffu, p3, src1);

            float a[4];
            a[0] = oddt ? u1 : u0;   // (row gid,   k tig)
            a[1] = oddt ? u3 : u2;   // (row gid+8, k tig)
            a[2] = oddt ? v1 : v0;   // (row gid,   k tig+4)
            a[3] = oddt ? v3 : v2;   // (row gid+8, k tig+4)

            const int kb = j * 8 + tig;
            #pragma unroll
            for (int jo = 0; jo < 8; jo++) {
                const int vb = (jo * 8 + gid) * APAD + kb;
                mma_tf32b(O[jo], a, VT[vb], VT[vb + 4]);
            }
        }
        __syncthreads();
    }

    // Finalize (tf32-round: feeds out-proj GEMM A operand)
    l0 += __shfl_xor_sync(0xffffffffu, l0, 1);
    l0 += __shfl_xor_sync(0xffffffffu, l0, 2);
    l1 += __shfl_xor_sync(0xffffffffu, l1, 1);
    l1 += __shfl_xor_sync(0xffffffffu, l1, 2);
    const float i0 = 1.0f / l0, i1 = 1.0f / l1;

    float* ob = out + ((size_t)(b * TT + r0g)) * CC + h * DD;
    #pragma unroll
    for (int j = 0; j < 8; j++) {
        const int cb = j * 8 + 2 * tig;
        *(float2*)(ob + cb) =
            make_float2(to_tf32(O[j][0] * i0), to_tf32(O[j][1] * i0));
        *(float2*)(ob + (size_t)8 * CC + cb) =
            make_float2(to_tf32(O[j][2] * i1), to_tf32(O[j][3] * i1));
    }
}

// ---------------------------------------------------------------------------
// Launch
// ---------------------------------------------------------------------------
extern "C" void kernel_launch(void* const* d_in, const int* in_sizes, int n_in,
                              void* d_out, int out_size)
{
    const float* x     = (const float*)d_in[0];
    const float* w_qkv = (const float*)d_in[1];
    const float* b_qkv = (const float*)d_in[2];
    const float* w_out = (const float*)d_in[3];
    const float* b_out = (const float*)d_in[4];
    float* out = (float*)d_out;

    float* qkv = nullptr;   cudaGetSymbolAddress((void**)&qkv, g_qkv);
    float* att = nullptr;   cudaGetSymbolAddress((void**)&att, g_att);
    float* x32 = nullptr;   cudaGetSymbolAddress((void**)&x32, g_x32);
    float* wqkvT = nullptr; cudaGetSymbolAddress((void**)&wqkvT, g_wqkvT);
    float* woutT = nullptr; cudaGetSymbolAddress((void**)&woutT, g_woutT);

    // Pre-round x; transpose+round weights
    {
        const int n = MM * CC;
        tf32_convert_kernel<<<n / (256 * 4), 256>>>(x, x32, n);
        dim3 blk(32, 8);
        transpose_kernel<<<dim3((3 * CC) / 32, CC / 32), blk>>>(w_qkv, wqkvT, CC, 3 * CC);
        transpose_kernel<<<dim3(CC / 32, CC / 32), blk>>>(w_out, woutT, CC, CC);
    }

    // QKV projection (tf32 mma, 2-stage)
    {
        dim3 grid((3 * CC) / GBN, MM / GBM);
        gemm_tf32_kernel<<<grid, 256>>>(x32, wqkvT, b_qkv, qkv, MM, 3 * CC, CC);
    }

    // Flash attention (hybrid bf16-S / tf32-PV)
    {
        dim3 grid(TT / 128, HH, BB);
        attn_hyb_kernel<<<grid, 256>>>(qkv, att);
    }

    // Output projection
    {
        dim3 grid(CC / GBN, MM / GBM);
        gemm_tf32_kernel<<<grid, 256>>>(att, woutT, b_out, out, MM, CC, CC);
    }
}

// round 9
// speedup vs baseline: 1.7024x; 1.0289x over previous
#include <cuda_runtime.h>
#include <cuda_bf16.h>
#include <cuda_fp16.h>
#include <cstdint>

// Problem constants
#define BB 4
#define TT 2048
#define CC 1024
#define HH 16
#define DD 64
#define MM (BB*TT)        // 8192

// Scratch (device globals: allocation-free rule)
__device__ float g_qkv[(size_t)MM * 3 * CC];     // [8192, 3072]
__device__ float g_att[(size_t)MM * CC];         // [8192, 1024] (tf32)
__device__ float g_x32[(size_t)MM * CC];         // tf32-rounded x
__device__ float g_wqkvT[(size_t)3 * CC * CC];   // [3072, 1024] (w_qkv^T, tf32)
__device__ float g_woutT[(size_t)CC * CC];       // [1024, 1024] (w_out^T, tf32)

// ---------------------------------------------------------------------------
// Helpers
// ---------------------------------------------------------------------------
__device__ __forceinline__ float to_tf32(float x) {
    uint32_t u;
    asm("cvt.rna.tf32.f32 %0, %1;" : "=r"(u) : "f"(x));
    return __uint_as_float(u);
}

__device__ __forceinline__ float ex2(float x) {
    float y;
    asm("ex2.approx.ftz.f32 %0, %1;" : "=f"(y) : "f"(x));
    return y;
}

// pack two f32 -> bf16x2 (x in low half)
__device__ __forceinline__ uint32_t pack_bf16x2(float x, float y) {
    uint32_t r;
    asm("cvt.rn.bf16x2.f32 %0, %1, %2;" : "=r"(r) : "f"(y), "f"(x));
    return r;
}

// pack two f32 -> f16x2 (x in low half)
__device__ __forceinline__ uint32_t pack_f16x2(float x, float y) {
    uint32_t r;
    asm("cvt.rn.f16x2.f32 %0, %1, %2;" : "=r"(r) : "f"(y), "f"(x));
    return r;
}

// split float pair into bf16x2 hi + bf16x2 residual
__device__ __forceinline__ void split_bf16(float x, float y,
                                           uint32_t& hi, uint32_t& lo) {
    __nv_bfloat16 hx = __float2bfloat16_rn(x);
    __nv_bfloat16 hy = __float2bfloat16_rn(y);
    float rx = x - __bfloat162float(hx);
    float ry = y - __bfloat162float(hy);
    hi = pack_bf16x2(__bfloat162float(hx), __bfloat162float(hy));
    lo = pack_bf16x2(rx, ry);
}

// m16n8k8 tf32 mma, fp32 accumulate
__device__ __forceinline__ void mma_tf32(float* c, const float* a, const float* b) {
    asm volatile(
        "mma.sync.aligned.m16n8k8.row.col.f32.tf32.tf32.f32 "
        "{%0,%1,%2,%3}, {%4,%5,%6,%7}, {%8,%9}, {%0,%1,%2,%3};\n"
        : "+f"(c[0]), "+f"(c[1]), "+f"(c[2]), "+f"(c[3])
        : "r"(__float_as_uint(a[0])), "r"(__float_as_uint(a[1])),
          "r"(__float_as_uint(a[2])), "r"(__float_as_uint(a[3])),
          "r"(__float_as_uint(b[0])), "r"(__float_as_uint(b[1])));
}

// m16n8k16 bf16 mma, fp32 accumulate
__device__ __forceinline__ void mma_bf16(float* c, const uint32_t* a,
                                         uint32_t b0, uint32_t b1) {
    asm volatile(
        "mma.sync.aligned.m16n8k16.row.col.f32.bf16.bf16.f32 "
        "{%0,%1,%2,%3}, {%4,%5,%6,%7}, {%8,%9}, {%0,%1,%2,%3};\n"
        : "+f"(c[0]), "+f"(c[1]), "+f"(c[2]), "+f"(c[3])
        : "r"(a[0]), "r"(a[1]), "r"(a[2]), "r"(a[3]),
          "r"(b0), "r"(b1));
}

// m16n8k16 f16 mma, fp32 accumulate
__device__ __forceinline__ void mma_f16(float* c, const uint32_t* a,
                                        uint32_t b0, uint32_t b1) {
    asm volatile(
        "mma.sync.aligned.m16n8k16.row.col.f32.f16.f16.f32 "
        "{%0,%1,%2,%3}, {%4,%5,%6,%7}, {%8,%9}, {%0,%1,%2,%3};\n"
        : "+f"(c[0]), "+f"(c[1]), "+f"(c[2]), "+f"(c[3])
        : "r"(a[0]), "r"(a[1]), "r"(a[2]), "r"(a[3]),
          "r"(b0), "r"(b1));
}

// ---------------------------------------------------------------------------
// Elementwise tf32 round
// ---------------------------------------------------------------------------
__global__ void tf32_convert_kernel(const float* __restrict__ in,
                                    float* __restrict__ out, int n)
{
    int i = (blockIdx.x * blockDim.x + threadIdx.x) * 4;
    if (i < n) {
        float4 v = *(const float4*)(in + i);
        v.x = to_tf32(v.x); v.y = to_tf32(v.y);
        v.z = to_tf32(v.z); v.w = to_tf32(v.w);
        *(float4*)(out + i) = v;
    }
}

// ---------------------------------------------------------------------------
// Weight transpose with tf32 rounding
// ---------------------------------------------------------------------------
__global__ void transpose_kernel(const float* __restrict__ in,
                                 float* __restrict__ out, int R, int C_)
{
    __shared__ float tile[32][33];
    const int c0 = blockIdx.x * 32, r0 = blockIdx.y * 32;
    const int tx = threadIdx.x, ty = threadIdx.y;   // 32 x 8
    #pragma unroll
    for (int i = 0; i < 32; i += 8)
        tile[ty + i][tx] = in[(size_t)(r0 + ty + i) * C_ + c0 + tx];
    __syncthreads();
    #pragma unroll
    for (int i = 0; i < 32; i += 8)
        out[(size_t)(c0 + ty + i) * R + r0 + tx] = to_tf32(tile[tx][ty + i]);
}

// ---------------------------------------------------------------------------
// tf32 mma.sync GEMM (measured 383us, unchanged): C = A @ Bt^T + bias
// ---------------------------------------------------------------------------
#define GBM 128
#define GBN 128
#define GBK 16
#define SPAD 20

__device__ __forceinline__ void cp_async16(uint32_t dst, const void* src) {
    asm volatile("cp.async.cg.shared.global [%0], [%1], 16;\n"
                 :: "r"(dst), "l"(src));
}
__device__ __forceinline__ void cp_commit() {
    asm volatile("cp.async.commit_group;\n" ::: "memory");
}
__device__ __forceinline__ void cp_wait1() {
    asm volatile("cp.async.wait_group 1;\n" ::: "memory");
}
__device__ __forceinline__ void cp_wait0() {
    asm volatile("cp.async.wait_group 0;\n" ::: "memory");
}

__device__ __forceinline__ uint32_t smem_u32(const void* p) {
    uint32_t a;
    asm("{ .reg .u64 t; cvta.to.shared.u64 t, %1; cvt.u32.u64 %0, t; }"
        : "=r"(a) : "l"(p));
    return a;
}

__global__ __launch_bounds__(256, 2)
void gemm_tf32_kernel(const float* __restrict__ A, const float* __restrict__ Bt,
                      const float* __restrict__ bias, float* __restrict__ C,
                      int M, int N, int K)
{
    __shared__ __align__(16) float As[2][GBM][SPAD];
    __shared__ __align__(16) float Bs[2][GBN][SPAD];

    const int tid  = threadIdx.x;
    const int wid  = tid >> 5;
    const int lane = tid & 31;
    const int gid  = lane >> 2;
    const int tig  = lane & 3;

    const int warp_m = wid & 1;
    const int warp_n = wid >> 1;

    const int brow = blockIdx.y, bcol = blockIdx.x;
    const float* Abase = A  + (size_t)brow * GBM * K;
    const float* Bbase = Bt + (size_t)bcol * GBN * K;

    float acc[4][4][4];
    #pragma unroll
    for (int i = 0; i < 4; i++)
        #pragma unroll
        for (int j = 0; j < 4; j++)
            #pragma unroll
            for (int r = 0; r < 4; r++) acc[i][j][r] = 0.0f;

    const uint32_t sA0 = smem_u32(&As[0][0][0]);
    const uint32_t sB0 = smem_u32(&Bs[0][0][0]);
    const uint32_t stageBytes = GBM * SPAD * 4;

    auto load_tile = [&](int it, int stage) {
        const int koff = it * GBK;
        #pragma unroll
        for (int q = 0; q < 2; q++) {
            const int idx = q * 256 + tid;
            const int row = idx >> 2;
            const int c4  = (idx & 3) * 4;
            const uint32_t doff = stage * stageBytes + (row * SPAD + c4) * 4;
            cp_async16(sA0 + doff, Abase + (size_t)row * K + koff + c4);
            cp_async16(sB0 + doff, Bbase + (size_t)row * K + koff + c4);
        }
    };

    const int nit = K / GBK;
    load_tile(0, 0);
    cp_commit();

    for (int it = 0; it < nit; ++it) {
        if (it + 1 < nit) {
            load_tile(it + 1, (it + 1) & 1);
            cp_commit();
            cp_wait1();
        } else {
            cp_wait0();
        }
        __syncthreads();

        const int st = it & 1;
        #pragma unroll
        for (int kk = 0; kk < GBK; kk += 8) {
            float a[4][4], b[4][2];
            #pragma unroll
            for (int i = 0; i < 4; i++) {
                const int r = warp_m * 64 + i * 16 + gid;
                a[i][0] = As[st][r][kk + tig];
                a[i][1] = As[st][r + 8][kk + tig];
                a[i][2] = As[st][r][kk + tig + 4];
                a[i][3] = As[st][r + 8][kk + tig + 4];
            }
            #pragma unroll
            for (int j = 0; j < 4; j++) {
                const int r = warp_n * 32 + j * 8 + gid;
                b[j][0] = Bs[st][r][kk + tig];
                b[j][1] = Bs[st][r][kk + tig + 4];
            }
            #pragma unroll
            for (int i = 0; i < 4; i++)
                #pragma unroll
                for (int j = 0; j < 4; j++)
                    mma_tf32(acc[i][j], a[i], b[j]);
        }
        __syncthreads();
    }

    #pragma unroll
    for (int i = 0; i < 4; i++) {
        const int row0 = brow * GBM + warp_m * 64 + i * 16 + gid;
        #pragma unroll
        for (int j = 0; j < 4; j++) {
            const int col = bcol * GBN + warp_n * 32 + j * 8 + 2 * tig;
            const float bx = bias[col], by = bias[col + 1];
            float2 v0 = make_float2(acc[i][j][0] + bx, acc[i][j][1] + by);
            float2 v1 = make_float2(acc[i][j][2] + bx, acc[i][j][3] + by);
            *(float2*)(C + (size_t)row0 * N + col) = v0;
            *(float2*)(C + (size_t)(row0 + 8) * N + col) = v1;
        }
    }
}

// ---------------------------------------------------------------------------
// Flash attention: bf16 3-term S + fp16 k16 PV (accumulator-layout identity).
// CTA: 128 q rows x one (b,h); 8 warps x 16 rows; kv tiles of 64.
// smem is pair-packed: operand words (k, k+4) adjacent -> all B-fragment
// loads are single LDS.64, conflict-free (pitch 20 u64 -> bank = 4*gid+tig).
//   KH/KL: 64 kv-rows x 16 u64 pairs (+4 pad)   (bf16 hi / residual)
//   VT:    64 d-rows  x 16 u64 pairs (+4 pad)   (fp16, kv-major pairs)
// ---------------------------------------------------------------------------
#define APAD 68          // f32 pitch for Q staging (one-time)
#define KP64 20          // u64 pitch for KH/KL/VT
#define KP32 40          // u32 pitch
#define ATTN_FLOATS (128 * APAD)   // 8704 floats; K/V region (7680) fits inside

__global__ __launch_bounds__(256, 2)
void attn_hyb_kernel(const float* __restrict__ qkv, float* __restrict__ out)
{
    __shared__ __align__(16) float dsm[ATTN_FLOATS];
    uint32_t* KH = (uint32_t*)dsm;          // u32 [0 .. 2560)
    uint32_t* KL = KH + 64 * KP32;          // u32 [2560 .. 5120)
    uint32_t* VT = KH + 2 * 64 * KP32;      // u32 [5120 .. 7680)
    __half*   VTh = (__half*)VT;

    const int qb = (int)gridDim.x - 1 - (int)blockIdx.x;  // heavy tiles first
    const int h  = blockIdx.y;
    const int b  = blockIdx.z;
    const int q0 = qb * 128;

    const int tid  = threadIdx.x;
    const int w    = tid >> 5;
    const int lane = tid & 31;
    const int gid  = lane >> 2;
    const int tig  = lane & 3;

    // Stage Q (scaled into exp2 domain, f32)
    const float SC = 0.125f * 1.4426950408889634f;
    {
        const float* qb_ptr = qkv + ((size_t)(b * TT + q0)) * (3 * CC) + h * DD;
        for (int idx = tid; idx < 128 * 16; idx += 256) {
            const int row = idx >> 4, c4 = (idx & 15) << 2;
            float4 v = *(const float4*)(qb_ptr + (size_t)row * (3 * CC) + c4);
            float* d = &dsm[row * APAD + c4];
            d[0] = v.x * SC; d[1] = v.y * SC;
            d[2] = v.z * SC; d[3] = v.w * SC;
        }
    }
    __syncthreads();

    const int r0l = w * 16 + gid;
    const int r0g = q0 + r0l;

    // Q hi/lo bf16 A-fragments: 4 k16-steps x 4 regs
    uint32_t qhi[4][4], qlo[4][4];
    #pragma unroll
    for (int ks = 0; ks < 4; ks++) {
        const int d0 = ks * 16 + 2 * tig;
        float2 x0 = *(float2*)&dsm[r0l * APAD + d0];
        float2 x1 = *(float2*)&dsm[(r0l + 8) * APAD + d0];
        float2 x2 = *(float2*)&dsm[r0l * APAD + d0 + 8];
        float2 x3 = *(float2*)&dsm[(r0l + 8) * APAD + d0 + 8];
        split_bf16(x0.x, x0.y, qhi[ks][0], qlo[ks][0]);
        split_bf16(x1.x, x1.y, qhi[ks][1], qlo[ks][1]);
        split_bf16(x2.x, x2.y, qhi[ks][2], qlo[ks][2]);
        split_bf16(x3.x, x3.y, qhi[ks][3], qlo[ks][3]);
    }
    __syncthreads();   // Q staging about to be overwritten by K/V

    float O[8][4];
    #pragma unroll
    for (int j = 0; j < 8; j++)
        #pragma unroll
        for (int r = 0; r < 4; r++) O[j][r] = 0.0f;
    float m0 = -1e30f, m1 = -1e30f, l0 = 0.0f, l1 = 0.0f;

    const int ntiles = 2 * (qb + 1);

    for (int t = 0; t < ntiles; t++) {
        const int kv0 = t * 64;

        // Stage K (bf16 hi/lo, pair-packed) and V (fp16, transposed pair-packed)
        for (int idx = tid; idx < 64 * 16; idx += 256) {
            const int row = idx >> 4, c4 = (idx & 15) << 2;
            const float* kp = qkv + ((size_t)(b * TT + kv0 + row)) * (3 * CC)
                              + CC + h * DD + c4;
            float4 k4 = *(const float4*)kp;
            float4 v4 = *(const float4*)(kp + CC);
            uint32_t h0, L0, h1, L1;
            split_bf16(k4.x, k4.y, h0, L0);
            split_bf16(k4.z, k4.w, h1, L1);
            // pair-packed slot for d-pair index u: (u>>3)*8 + 2*(u&3) + ((u&7)>>2)
            const int u0 = c4 >> 1, u1 = u0 + 1;
            const int s0 = row * KP32 + ((u0 >> 3) << 3) + ((u0 & 3) << 1) + ((u0 & 7) >> 2);
            const int s1 = row * KP32 + ((u1 >> 3) << 3) + ((u1 & 3) << 1) + ((u1 & 7) >> 2);
            KH[s0] = h0; KL[s0] = L0;
            KH[s1] = h1; KL[s1] = L1;
            // V: fp16 halves; kv u32-pair wv=row>>1 (half=row&1), slot by same rule
            const int wv = row >> 1, hf = row & 1;
            const int vs = ((wv >> 3) << 3) + ((wv & 3) << 1) + ((wv & 7) >> 2);
            VTh[(c4 + 0) * (KP32 * 2) + 2 * vs + hf] = __float2half_rn(v4.x);
            VTh[(c4 + 1) * (KP32 * 2) + 2 * vs + hf] = __float2half_rn(v4.y);
            VTh[(c4 + 2) * (KP32 * 2) + 2 * vs + hf] = __float2half_rn(v4.z);
            VTh[(c4 + 3) * (KP32 * 2) + 2 * vs + hf] = __float2half_rn(v4.w);
        }
        __syncthreads();

        // S = Q @ K^T (bf16 3-term), B-frags via single LDS.64
        float s[8][4];
        #pragma unroll
        for (int j = 0; j < 8; j++)
            #pragma unroll
            for (int r = 0; r < 4; r++) s[j][r] = 0.0f;

        const uint2* KH2 = (const uint2*)KH;
        const uint2* KL2 = (const uint2*)KL;
        #pragma unroll
        for (int ks = 0; ks < 4; ks++) {
            #pragma unroll
            for (int j = 0; j < 8; j++) {
                const int pb = (j * 8 + gid) * KP64 + ks * 4 + tig;
                const uint2 bh = KH2[pb];
                const uint2 bl = KL2[pb];
                mma_bf16(s[j], qhi[ks], bh.x, bh.y);
                mma_bf16(s[j], qhi[ks], bl.x, bl.y);
                mma_bf16(s[j], qlo[ks], bh.x, bh.y);
            }
        }

        // Causal mask on the two diagonal-straddling tiles
        if (t + 2 >= ntiles) {
            #pragma unroll
            for (int j = 0; j < 8; j++) {
                const int col = kv0 + j * 8 + 2 * tig;
                if (col     > r0g)     s[j][0] = -1e30f;
                if (col + 1 > r0g)     s[j][1] = -1e30f;
                if (col     > r0g + 8) s[j][2] = -1e30f;
                if (col + 1 > r0g + 8) s[j][3] = -1e30f;
            }
        }

        // Online softmax (exp2 domain)
        float mt0 = s[0][0], mt1 = s[0][2];
        #pragma unroll
        for (int j = 0; j < 8; j++) {
            mt0 = fmaxf(mt0, fmaxf(s[j][0], s[j][1]));
            mt1 = fmaxf(mt1, fmaxf(s[j][2], s[j][3]));
        }
        mt0 = fmaxf(mt0, __shfl_xor_sync(0xffffffffu, mt0, 1));
        mt0 = fmaxf(mt0, __shfl_xor_sync(0xffffffffu, mt0, 2));
        mt1 = fmaxf(mt1, __shfl_xor_sync(0xffffffffu, mt1, 1));
        mt1 = fmaxf(mt1, __shfl_xor_sync(0xffffffffu, mt1, 2));

        const float mn0 = fmaxf(m0, mt0), mn1 = fmaxf(m1, mt1);
        const float c0 = ex2(m0 - mn0), c1 = ex2(m1 - mn1);
        l0 *= c0; l1 *= c1;
        #pragma unroll
        for (int j = 0; j < 8; j++) {
            O[j][0] *= c0; O[j][1] *= c0;
            O[j][2] *= c1; O[j][3] *= c1;
        }
        m0 = mn0; m1 = mn1;

        // Exponentiate in place, accumulate l
        #pragma unroll
        for (int j = 0; j < 8; j++) {
            s[j][0] = ex2(s[j][0] - mn0);
            s[j][1] = ex2(s[j][1] - mn0);
            s[j][2] = ex2(s[j][2] - mn1);
            s[j][3] = ex2(s[j][3] - mn1);
            l0 += s[j][0] + s[j][1];
            l1 += s[j][2] + s[j][3];
        }

        // PV: fp16 k16, P packs directly into A-fragments (layout identity)
        const uint2* VT2 = (const uint2*)VT;
        #pragma unroll
        for (int jk = 0; jk < 4; jk++) {
            uint32_t a[4];
            a[0] = pack_f16x2(s[2 * jk][0],     s[2 * jk][1]);
            a[1] = pack_f16x2(s[2 * jk][2],     s[2 * jk][3]);
            a[2] = pack_f16x2(s[2 * jk + 1][0], s[2 * jk + 1][1]);
            a[3] = pack_f16x2(s[2 * jk + 1][2], s[2 * jk + 1][3]);
            #pragma unroll
            for (int jo = 0; jo < 8; jo++) {
                const uint2 vv = VT2[(jo * 8 + gid) * KP64 + jk * 4 + tig];
                mma_f16(O[jo], a, vv.x, vv.y);
            }
        }
        __syncthreads();
    }

    // Finalize (tf32-round: feeds out-proj GEMM A operand)
    l0 += __shfl_xor_sync(0xffffffffu, l0, 1);
    l0 += __shfl_xor_sync(0xffffffffu, l0, 2);
    l1 += __shfl_xor_sync(0xffffffffu, l1, 1);
    l1 += __shfl_xor_sync(0xffffffffu, l1, 2);
    const float i0 = 1.0f / l0, i1 = 1.0f / l1;

    float* ob = out + ((size_t)(b * TT + r0g)) * CC + h * DD;
    #pragma unroll
    for (int j = 0; j < 8; j++) {
        const int cb = j * 8 + 2 * tig;
        *(float2*)(ob + cb) =
            make_float2(to_tf32(O[j][0] * i0), to_tf32(O[j][1] * i0));
        *(float2*)(ob + (size_t)8 * CC + cb) =
            make_float2(to_tf32(O[j][2] * i1), to_tf32(O[j][3] * i1));
    }
}

// ---------------------------------------------------------------------------
// Launch
// ---------------------------------------------------------------------------
extern "C" void kernel_launch(void* const* d_in, const int* in_sizes, int n_in,
                              void* d_out, int out_size)
{
    const float* x     = (const float*)d_in[0];
    const float* w_qkv = (const float*)d_in[1];
    const float* b_qkv = (const float*)d_in[2];
    const float* w_out = (const float*)d_in[3];
    const float* b_out = (const float*)d_in[4];
    float* out = (float*)d_out;

    float* qkv = nullptr;   cudaGetSymbolAddress((void**)&qkv, g_qkv);
    float* att = nullptr;   cudaGetSymbolAddress((void**)&att, g_att);
    float* x32 = nullptr;   cudaGetSymbolAddress((void**)&x32, g_x32);
    float* wqkvT = nullptr; cudaGetSymbolAddress((void**)&wqkvT, g_wqkvT);
    float* woutT = nullptr; cudaGetSymbolAddress((void**)&woutT, g_woutT);

    // Pre-round x; transpose+round weights
    {
        const int n = MM * CC;
        tf32_convert_kernel<<<n / (256 * 4), 256>>>(x, x32, n);
        dim3 blk(32, 8);
        transpose_kernel<<<dim3((3 * CC) / 32, CC / 32), blk>>>(w_qkv, wqkvT, CC, 3 * CC);
        transpose_kernel<<<dim3(CC / 32, CC / 32), blk>>>(w_out, woutT, CC, CC);
    }

    // QKV projection (tf32 mma, 2-stage)
    {
        dim3 grid((3 * CC) / GBN, MM / GBM);
        gemm_tf32_kernel<<<grid, 256>>>(x32, wqkvT, b_qkv, qkv, MM, 3 * CC, CC);
    }

    // Flash attention (bf16-S / fp16-PV, pair-packed smem)
    {
        dim3 grid(TT / 128, HH, BB);
        attn_hyb_kernel<<<grid, 256>>>(qkv, att);
    }

    // Output projection
    {
        dim3 grid(CC / GBN, MM / GBM);
        gemm_tf32_kernel<<<grid, 256>>>(att, woutT, b_out, out, MM, CC, CC);
    }
}

// round 10
// speedup vs baseline: 2.3966x; 1.4078x over previous
#include <cuda_runtime.h>
#include <cuda_bf16.h>
#include <cuda_fp16.h>
#include <cstdint>

// Problem constants
#define BB 4
#define TT 2048
#define CC 1024
#define HH 16
#define DD 64
#define MM (BB*TT)        // 8192

// Scratch (device globals: allocation-free rule)
__device__ float  g_qkv[(size_t)MM * 3 * CC];      // [8192, 3072] fp32
__device__ __half g_att16[(size_t)MM * CC];        // [8192, 1024] fp16 perm
__device__ __half g_x16[(size_t)MM * CC];          // fp16 perm x
__device__ __half g_wqkvT16[(size_t)3 * CC * CC];  // [3072,1024] fp16 perm
__device__ __half g_woutT16[(size_t)CC * CC];      // [1024,1024] fp16 perm

// ---------------------------------------------------------------------------
// Helpers
// ---------------------------------------------------------------------------
__device__ __forceinline__ float ex2(float x) {
    float y;
    asm("ex2.approx.ftz.f32 %0, %1;" : "=f"(y) : "f"(x));
    return y;
}

__device__ __forceinline__ uint32_t pack_bf16x2(float x, float y) {
    uint32_t r;
    asm("cvt.rn.bf16x2.f32 %0, %1, %2;" : "=r"(r) : "f"(y), "f"(x));
    return r;
}

__device__ __forceinline__ uint32_t pack_f16x2(float x, float y) {
    uint32_t r;
    asm("cvt.rn.f16x2.f32 %0, %1, %2;" : "=r"(r) : "f"(y), "f"(x));
    return r;
}

__device__ __forceinline__ void split_bf16(float x, float y,
                                           uint32_t& hi, uint32_t& lo) {
    __nv_bfloat16 hx = __float2bfloat16_rn(x);
    __nv_bfloat16 hy = __float2bfloat16_rn(y);
    float rx = x - __bfloat162float(hx);
    float ry = y - __bfloat162float(hy);
    hi = pack_bf16x2(__bfloat162float(hx), __bfloat162float(hy));
    lo = pack_bf16x2(rx, ry);
}

// m16n8k16 bf16 mma, fp32 accumulate
__device__ __forceinline__ void mma_bf16(float* c, const uint32_t* a,
                                         uint32_t b0, uint32_t b1) {
    asm volatile(
        "mma.sync.aligned.m16n8k16.row.col.f32.bf16.bf16.f32 "
        "{%0,%1,%2,%3}, {%4,%5,%6,%7}, {%8,%9}, {%0,%1,%2,%3};\n"
        : "+f"(c[0]), "+f"(c[1]), "+f"(c[2]), "+f"(c[3])
        : "r"(a[0]), "r"(a[1]), "r"(a[2]), "r"(a[3]),
          "r"(b0), "r"(b1));
}

// m16n8k16 f16 mma, fp32 accumulate
__device__ __forceinline__ void mma_f16(float* c, const uint32_t* a,
                                        uint32_t b0, uint32_t b1) {
    asm volatile(
        "mma.sync.aligned.m16n8k16.row.col.f32.f16.f16.f32 "
        "{%0,%1,%2,%3}, {%4,%5,%6,%7}, {%8,%9}, {%0,%1,%2,%3};\n"
        : "+f"(c[0]), "+f"(c[1]), "+f"(c[2]), "+f"(c[3])
        : "r"(a[0]), "r"(a[1]), "r"(a[2]), "r"(a[3]),
          "r"(b0), "r"(b1));
}

__device__ __forceinline__ void cp_async16(uint32_t dst, const void* src) {
    asm volatile("cp.async.cg.shared.global [%0], [%1], 16;\n"
                 :: "r"(dst), "l"(src));
}
__device__ __forceinline__ void cp_commit() {
    asm volatile("cp.async.commit_group;\n" ::: "memory");
}
__device__ __forceinline__ void cp_wait1() {
    asm volatile("cp.async.wait_group 1;\n" ::: "memory");
}
__device__ __forceinline__ void cp_wait0() {
    asm volatile("cp.async.wait_group 0;\n" ::: "memory");
}

__device__ __forceinline__ uint32_t smem_u32(const void* p) {
    uint32_t a;
    asm("{ .reg .u64 t; cvta.to.shared.u64 t, %1; cvt.u32.u64 %0, t; }"
        : "=r"(a) : "l"(p));
    return a;
}

// pair-pack slot for u32-pair index u (0..7) within a 16-half group:
// slot(u) = 2*(u&3) + (u>>2); u64 slot s holds u32 pairs {u=s, u=s+4}
__device__ __forceinline__ int pp_slot(int u) {
    return 2 * (u & 3) + (u >> 2);
}

// ---------------------------------------------------------------------------
// x -> fp16 pair-pack-permuted. One thread per 16-half group.
// Group layout (u32 units): out[s] = pack(f[2u], f[2u+1]), u = (s>>1)+(s&1)*4
// ---------------------------------------------------------------------------
__global__ void f16perm_convert_kernel(const float* __restrict__ in,
                                       __half* __restrict__ out, int ngroups)
{
    int g = blockIdx.x * blockDim.x + threadIdx.x;
    if (g >= ngroups) return;
    const float* src = in + (size_t)g * 16;
    float f[16];
    #pragma unroll
    for (int i = 0; i < 16; i += 4)
        *(float4*)&f[i] = *(const float4*)(src + i);
    uint32_t u[8];
    #pragma unroll
    for (int s = 0; s < 8; s++) {
        const int uu = (s >> 1) + (s & 1) * 4;
        u[s] = pack_f16x2(f[2 * uu], f[2 * uu + 1]);
    }
    uint4* dst = (uint4*)(out + (size_t)g * 16);
    dst[0] = make_uint4(u[0], u[1], u[2], u[3]);
    dst[1] = make_uint4(u[4], u[5], u[6], u[7]);
}

// ---------------------------------------------------------------------------
// Weight transpose -> fp16 pair-pack-permuted [N,K] rows
// ---------------------------------------------------------------------------
__global__ void transpose_f16perm_kernel(const float* __restrict__ in,
                                         __half* __restrict__ out, int R, int C_)
{
    __shared__ float tile[32][33];
    const int c0 = blockIdx.x * 32, r0 = blockIdx.y * 32;
    const int tx = threadIdx.x, ty = threadIdx.y;   // 32 x 8
    #pragma unroll
    for (int i = 0; i < 32; i += 8)
        tile[ty + i][tx] = in[(size_t)(r0 + ty + i) * C_ + c0 + tx];
    __syncthreads();
    const int k = r0 + tx;
    const int pk = (k & ~15) + pp_slot((k >> 1) & 7) * 2 + (k & 1);
    #pragma unroll
    for (int i = 0; i < 32; i += 8)
        out[(size_t)(c0 + ty + i) * R + pk] = __float2half_rn(tile[tx][ty + i]);
}

// ---------------------------------------------------------------------------
// fp16 mma.sync GEMM: C[M,N] = A[M,K] @ Bt[N,K]^T + bias[N]
// A, Bt fp16 pair-pack-permuted. 128x128 CTA tile, BK=32, 256 threads,
// 2-stage cp.async. smem pitch 12 u64/row (8 data + 4 pad, conflict-free).
// ---------------------------------------------------------------------------
#define GBM 128
#define GBK 32
#define GP64 12   // u64 pitch per row

__global__ __launch_bounds__(256, 2)
void gemm_f16_kernel(const __half* __restrict__ A, const __half* __restrict__ Bt,
                     const float* __restrict__ bias, float* __restrict__ C,
                     int M, int N, int K)
{
    __shared__ __align__(16) uint2 As[2][GBM * GP64];
    __shared__ __align__(16) uint2 Bs[2][GBM * GP64];

    const int tid  = threadIdx.x;
    const int wid  = tid >> 5;
    const int lane = tid & 31;
    const int gid  = lane >> 2;
    const int tig  = lane & 3;

    const int warp_m = wid & 1;    // 64 rows each
    const int warp_n = wid >> 1;   // 32 cols each

    const int brow = blockIdx.y, bcol = blockIdx.x;
    const __half* Abase = A  + (size_t)brow * GBM * K;
    const __half* Bbase = Bt + (size_t)bcol * GBM * K;

    float acc[4][4][4];
    #pragma unroll
    for (int i = 0; i < 4; i++)
        #pragma unroll
        for (int j = 0; j < 4; j++)
            #pragma unroll
            for (int r = 0; r < 4; r++) acc[i][j][r] = 0.0f;

    // loader: per matrix per stage, 128 rows x 64 B = 512 x 16B chunks
    auto load_tile = [&](int it, int stage) {
        const int koff = it * GBK;   // halves
        #pragma unroll
        for (int q = 0; q < 2; q++) {
            const int idx = q * 256 + tid;       // 0..511
            const int row = idx >> 2;            // 0..127
            const int grp = (idx >> 1) & 1;      // k16 group within BK=32
            const int hf  = idx & 1;             // 16B half of the 32B group
            const int ds  = row * GP64 + grp * 4 + hf * 2;
            cp_async16(smem_u32(&As[stage][ds]),
                       Abase + (size_t)row * K + koff + grp * 16 + hf * 8);
            cp_async16(smem_u32(&Bs[stage][ds]),
                       Bbase + (size_t)row * K + koff + grp * 16 + hf * 8);
        }
    };

    const int nit = K / GBK;
    load_tile(0, 0);
    cp_commit();

    for (int it = 0; it < nit; ++it) {
        if (it + 1 < nit) {
            load_tile(it + 1, (it + 1) & 1);
            cp_commit();
            cp_wait1();
        } else {
            cp_wait0();
        }
        __syncthreads();

        const int st = it & 1;
        #pragma unroll
        for (int kk = 0; kk < 2; kk++) {       // two k16 groups
            uint32_t a[4][4];
            uint32_t b[4][2];
            #pragma unroll
            for (int i = 0; i < 4; i++) {
                const int r = warp_m * 64 + i * 16 + gid;
                const uint2 a02 = As[st][r * GP64 + kk * 4 + tig];
                const uint2 a13 = As[st][(r + 8) * GP64 + kk * 4 + tig];
                a[i][0] = a02.x; a[i][1] = a13.x;
                a[i][2] = a02.y; a[i][3] = a13.y;
            }
            #pragma unroll
            for (int j = 0; j < 4; j++) {
                const int rn = warp_n * 32 + j * 8 + gid;
                const uint2 bb = Bs[st][rn * GP64 + kk * 4 + tig];
                b[j][0] = bb.x; b[j][1] = bb.y;
            }
            #pragma unroll
            for (int i = 0; i < 4; i++)
                #pragma unroll
                for (int j = 0; j < 4; j++)
                    mma_f16(acc[i][j], a[i], b[j][0], b[j][1]);
        }
        __syncthreads();
    }

    #pragma unroll
    for (int i = 0; i < 4; i++) {
        const int row0 = brow * GBM + warp_m * 64 + i * 16 + gid;
        #pragma unroll
        for (int j = 0; j < 4; j++) {
            const int col = bcol * GBM + warp_n * 32 + j * 8 + 2 * tig;
            const float bx = bias[col], by = bias[col + 1];
            float2 v0 = make_float2(acc[i][j][0] + bx, acc[i][j][1] + by);
            float2 v1 = make_float2(acc[i][j][2] + bx, acc[i][j][3] + by);
            *(float2*)(C + (size_t)row0 * N + col) = v0;
            *(float2*)(C + (size_t)(row0 + 8) * N + col) = v1;
        }
    }
}

// ---------------------------------------------------------------------------
// Flash attention: bf16 3-term S + fp16 k16 PV (round-9 passing version).
// Only change: epilogue writes fp16 pair-pack-permuted into g_att16.
// ---------------------------------------------------------------------------
#define APAD 68          // f32 pitch for Q staging (one-time)
#define KP64 20          // u64 pitch for KH/KL/VT
#define KP32 40          // u32 pitch
#define ATTN_FLOATS (128 * APAD)

__global__ __launch_bounds__(256, 2)
void attn_hyb_kernel(const float* __restrict__ qkv, __half* __restrict__ out)
{
    __shared__ __align__(16) float dsm[ATTN_FLOATS];
    uint32_t* KH = (uint32_t*)dsm;
    uint32_t* KL = KH + 64 * KP32;
    uint32_t* VT = KH + 2 * 64 * KP32;
    __half*   VTh = (__half*)VT;

    const int qb = (int)gridDim.x - 1 - (int)blockIdx.x;
    const int h  = blockIdx.y;
    const int b  = blockIdx.z;
    const int q0 = qb * 128;

    const int tid  = threadIdx.x;
    const int w    = tid >> 5;
    const int lane = tid & 31;
    const int gid  = lane >> 2;
    const int tig  = lane & 3;

    const float SC = 0.125f * 1.4426950408889634f;
    {
        const float* qb_ptr = qkv + ((size_t)(b * TT + q0)) * (3 * CC) + h * DD;
        for (int idx = tid; idx < 128 * 16; idx += 256) {
            const int row = idx >> 4, c4 = (idx & 15) << 2;
            float4 v = *(const float4*)(qb_ptr + (size_t)row * (3 * CC) + c4);
            float* d = &dsm[row * APAD + c4];
            d[0] = v.x * SC; d[1] = v.y * SC;
            d[2] = v.z * SC; d[3] = v.w * SC;
        }
    }
    __syncthreads();

    const int r0l = w * 16 + gid;
    const int r0g = q0 + r0l;

    uint32_t qhi[4][4], qlo[4][4];
    #pragma unroll
    for (int ks = 0; ks < 4; ks++) {
        const int d0 = ks * 16 + 2 * tig;
        float2 x0 = *(float2*)&dsm[r0l * APAD + d0];
        float2 x1 = *(float2*)&dsm[(r0l + 8) * APAD + d0];
        float2 x2 = *(float2*)&dsm[r0l * APAD + d0 + 8];
        float2 x3 = *(float2*)&dsm[(r0l + 8) * APAD + d0 + 8];
        split_bf16(x0.x, x0.y, qhi[ks][0], qlo[ks][0]);
        split_bf16(x1.x, x1.y, qhi[ks][1], qlo[ks][1]);
        split_bf16(x2.x, x2.y, qhi[ks][2], qlo[ks][2]);
        split_bf16(x3.x, x3.y, qhi[ks][3], qlo[ks][3]);
    }
    __syncthreads();

    float O[8][4];
    #pragma unroll
    for (int j = 0; j < 8; j++)
        #pragma unroll
        for (int r = 0; r < 4; r++) O[j][r] = 0.0f;
    float m0 = -1e30f, m1 = -1e30f, l0 = 0.0f, l1 = 0.0f;

    const int ntiles = 2 * (qb + 1);

    for (int t = 0; t < ntiles; t++) {
        const int kv0 = t * 64;

        for (int idx = tid; idx < 64 * 16; idx += 256) {
            const int row = idx >> 4, c4 = (idx & 15) << 2;
            const float* kp = qkv + ((size_t)(b * TT + kv0 + row)) * (3 * CC)
                              + CC + h * DD + c4;
            float4 k4 = *(const float4*)kp;
            float4 v4 = *(const float4*)(kp + CC);
            uint32_t h0, L0, h1, L1;
            split_bf16(k4.x, k4.y, h0, L0);
            split_bf16(k4.z, k4.w, h1, L1);
            const int u0 = c4 >> 1, u1 = u0 + 1;
            const int s0 = row * KP32 + ((u0 >> 3) << 3) + ((u0 & 3) << 1) + ((u0 & 7) >> 2);
            const int s1 = row * KP32 + ((u1 >> 3) << 3) + ((u1 & 3) << 1) + ((u1 & 7) >> 2);
            KH[s0] = h0; KL[s0] = L0;
            KH[s1] = h1; KL[s1] = L1;
            const int wv = row >> 1, hf = row & 1;
            const int vs = ((wv >> 3) << 3) + ((wv & 3) << 1) + ((wv & 7) >> 2);
            VTh[(c4 + 0) * (KP32 * 2) + 2 * vs + hf] = __float2half_rn(v4.x);
            VTh[(c4 + 1) * (KP32 * 2) + 2 * vs + hf] = __float2half_rn(v4.y);
            VTh[(c4 + 2) * (KP32 * 2) + 2 * vs + hf] = __float2half_rn(v4.z);
            VTh[(c4 + 3) * (KP32 * 2) + 2 * vs + hf] = __float2half_rn(v4.w);
        }
        __syncthreads();

        float s[8][4];
        #pragma unroll
        for (int j = 0; j < 8; j++)
            #pragma unroll
            for (int r = 0; r < 4; r++) s[j][r] = 0.0f;

        const uint2* KH2 = (const uint2*)KH;
        const uint2* KL2 = (const uint2*)KL;
        #pragma unroll
        for (int ks = 0; ks < 4; ks++) {
            #pragma unroll
            for (int j = 0; j < 8; j++) {
                const int pb = (j * 8 + gid) * KP64 + ks * 4 + tig;
                const uint2 bh = KH2[pb];
                const uint2 bl = KL2[pb];
                mma_bf16(s[j], qhi[ks], bh.x, bh.y);
                mma_bf16(s[j], qhi[ks], bl.x, bl.y);
                mma_bf16(s[j], qlo[ks], bh.x, bh.y);
            }
        }

        if (t + 2 >= ntiles) {
            #pragma unroll
            for (int j = 0; j < 8; j++) {
                const int col = kv0 + j * 8 + 2 * tig;
                if (col     > r0g)     s[j][0] = -1e30f;
                if (col + 1 > r0g)     s[j][1] = -1e30f;
                if (col     > r0g + 8) s[j][2] = -1e30f;
                if (col + 1 > r0g + 8) s[j][3] = -1e30f;
            }
        }

        float mt0 = s[0][0], mt1 = s[0][2];
        #pragma unroll
        for (int j = 0; j < 8; j++) {
            mt0 = fmaxf(mt0, fmaxf(s[j][0], s[j][1]));
            mt1 = fmaxf(mt1, fmaxf(s[j][2], s[j][3]));
        }
        mt0 = fmaxf(mt0, __shfl_xor_sync(0xffffffffu, mt0, 1));
        mt0 = fmaxf(mt0, __shfl_xor_sync(0xffffffffu, mt0, 2));
        mt1 = fmaxf(mt1, __shfl_xor_sync(0xffffffffu, mt1, 1));
        mt1 = fmaxf(mt1, __shfl_xor_sync(0xffffffffu, mt1, 2));

        const float mn0 = fmaxf(m0, mt0), mn1 = fmaxf(m1, mt1);
        const float c0 = ex2(m0 - mn0), c1 = ex2(m1 - mn1);
        l0 *= c0; l1 *= c1;
        #pragma unroll
        for (int j = 0; j < 8; j++) {
            O[j][0] *= c0; O[j][1] *= c0;
            O[j][2] *= c1; O[j][3] *= c1;
        }
        m0 = mn0; m1 = mn1;

        #pragma unroll
        for (int j = 0; j < 8; j++) {
            s[j][0] = ex2(s[j][0] - mn0);
            s[j][1] = ex2(s[j][1] - mn0);
            s[j][2] = ex2(s[j][2] - mn1);
            s[j][3] = ex2(s[j][3] - mn1);
            l0 += s[j][0] + s[j][1];
            l1 += s[j][2] + s[j][3];
        }

        const uint2* VT2 = (const uint2*)VT;
        #pragma unroll
        for (int jk = 0; jk < 4; jk++) {
            uint32_t a[4];
            a[0] = pack_f16x2(s[2 * jk][0],     s[2 * jk][1]);
            a[1] = pack_f16x2(s[2 * jk][2],     s[2 * jk][3]);
            a[2] = pack_f16x2(s[2 * jk + 1][0], s[2 * jk + 1][1]);
            a[3] = pack_f16x2(s[2 * jk + 1][2], s[2 * jk + 1][3]);
            #pragma unroll
            for (int jo = 0; jo < 8; jo++) {
                const uint2 vv = VT2[(jo * 8 + gid) * KP64 + jk * 4 + tig];
                mma_f16(O[jo], a, vv.x, vv.y);
            }
        }
        __syncthreads();
    }

    // Finalize: write fp16 pair-pack-permuted rows into g_att16
    l0 += __shfl_xor_sync(0xffffffffu, l0, 1);
    l0 += __shfl_xor_sync(0xffffffffu, l0, 2);
    l1 += __shfl_xor_sync(0xffffffffu, l1, 1);
    l1 += __shfl_xor_sync(0xffffffffu, l1, 2);
    const float i0 = 1.0f / l0, i1 = 1.0f / l1;

    __half* ob = out + ((size_t)(b * TT + r0g)) * CC + h * DD;
    #pragma unroll
    for (int j = 0; j < 8; j++) {
        // local col pair u = (j&1)*4 + tig within group j>>1
        const int off = ((j >> 1) << 4) + ((2 * tig + (j & 1)) << 1);
        *(uint32_t*)(ob + off) =
            pack_f16x2(O[j][0] * i0, O[j][1] * i0);
        *(uint32_t*)(ob + (size_t)8 * CC + off) =
            pack_f16x2(O[j][2] * i1, O[j][3] * i1);
    }
}

// ---------------------------------------------------------------------------
// Launch
// ---------------------------------------------------------------------------
extern "C" void kernel_launch(void* const* d_in, const int* in_sizes, int n_in,
                              void* d_out, int out_size)
{
    const float* x     = (const float*)d_in[0];
    const float* w_qkv = (const float*)d_in[1];
    const float* b_qkv = (const float*)d_in[2];
    const float* w_out = (const float*)d_in[3];
    const float* b_out = (const float*)d_in[4];
    float* out = (float*)d_out;

    float*  qkv = nullptr;    cudaGetSymbolAddress((void**)&qkv, g_qkv);
    __half* att16 = nullptr;  cudaGetSymbolAddress((void**)&att16, g_att16);
    __half* x16 = nullptr;    cudaGetSymbolAddress((void**)&x16, g_x16);
    __half* wqkvT = nullptr;  cudaGetSymbolAddress((void**)&wqkvT, g_wqkvT16);
    __half* woutT = nullptr;  cudaGetSymbolAddress((void**)&woutT, g_woutT16);

    // Preproc: x -> fp16 perm; weights -> transposed fp16 perm
    {
        const int ngroups = MM * CC / 16;
        f16perm_convert_kernel<<<ngroups / 256, 256>>>(x, x16, ngroups);
        dim3 blk(32, 8);
        transpose_f16perm_kernel<<<dim3((3 * CC) / 32, CC / 32), blk>>>(w_qkv, wqkvT, CC, 3 * CC);
        transpose_f16perm_kernel<<<dim3(CC / 32, CC / 32), blk>>>(w_out, woutT, CC, CC);
    }

    // QKV projection (fp16 mma)
    {
        dim3 grid((3 * CC) / 128, MM / 128);
        gemm_f16_kernel<<<grid, 256>>>(x16, wqkvT, b_qkv, qkv, MM, 3 * CC, CC);
    }

    // Flash attention (bf16-S / fp16-PV)
    {
        dim3 grid(TT / 128, HH, BB);
        attn_hyb_kernel<<<grid, 256>>>(qkv, att16);
    }

    // Output projection (fp16 mma)
    {
        dim3 grid(CC / 128, MM / 128);
        gemm_f16_kernel<<<grid, 256>>>(att16, woutT, b_out, out, MM, CC, CC);
    }
}

// round 11
// speedup vs baseline: 3.3101x; 1.3812x over previous
#include <cuda_runtime.h>
#include <cuda_bf16.h>
#include <cuda_fp16.h>
#include <cstdint>

// Problem constants
#define BB 4
#define TT 2048
#define CC 1024
#define HH 16
#define DD 64
#define MM (BB*TT)        // 8192

#define SCALE_EXP2 0.1803368801111204f   // 0.125 * log2(e)

// Scratch (device globals: allocation-free rule)
__device__ float    g_q[(size_t)MM * CC];        // prescaled fp32 Q
__device__ uint32_t g_kh[(size_t)MM * CC / 2];   // bf16-hi pair-packed K
__device__ uint32_t g_kl[(size_t)MM * CC / 2];   // bf16-lo pair-packed K
__device__ __half   g_v16[(size_t)MM * CC];      // fp16 V, [b,tile,h][d][tk_perm]
__device__ __half   g_att16[(size_t)MM * CC];    // attention out, fp16 perm
__device__ __half   g_x16[(size_t)MM * CC];      // fp16 perm x
__device__ __half   g_wqkvT16[(size_t)3 * CC * CC];
__device__ __half   g_woutT16[(size_t)CC * CC];

// ---------------------------------------------------------------------------
// Helpers
// ---------------------------------------------------------------------------
__device__ __forceinline__ float ex2(float x) {
    float y;
    asm("ex2.approx.ftz.f32 %0, %1;" : "=f"(y) : "f"(x));
    return y;
}

__device__ __forceinline__ uint32_t pack_bf16x2(float x, float y) {
    uint32_t r;
    asm("cvt.rn.bf16x2.f32 %0, %1, %2;" : "=r"(r) : "f"(y), "f"(x));
    return r;
}

__device__ __forceinline__ uint32_t pack_f16x2(float x, float y) {
    uint32_t r;
    asm("cvt.rn.f16x2.f32 %0, %1, %2;" : "=r"(r) : "f"(y), "f"(x));
    return r;
}

__device__ __forceinline__ void split_bf16(float x, float y,
                                           uint32_t& hi, uint32_t& lo) {
    __nv_bfloat16 hx = __float2bfloat16_rn(x);
    __nv_bfloat16 hy = __float2bfloat16_rn(y);
    float rx = x - __bfloat162float(hx);
    float ry = y - __bfloat162float(hy);
    hi = pack_bf16x2(__bfloat162float(hx), __bfloat162float(hy));
    lo = pack_bf16x2(rx, ry);
}

__device__ __forceinline__ void mma_bf16(float* c, const uint32_t* a,
                                         uint32_t b0, uint32_t b1) {
    asm volatile(
        "mma.sync.aligned.m16n8k16.row.col.f32.bf16.bf16.f32 "
        "{%0,%1,%2,%3}, {%4,%5,%6,%7}, {%8,%9}, {%0,%1,%2,%3};\n"
        : "+f"(c[0]), "+f"(c[1]), "+f"(c[2]), "+f"(c[3])
        : "r"(a[0]), "r"(a[1]), "r"(a[2]), "r"(a[3]),
          "r"(b0), "r"(b1));
}

__device__ __forceinline__ void mma_f16(float* c, const uint32_t* a,
                                        uint32_t b0, uint32_t b1) {
    asm volatile(
        "mma.sync.aligned.m16n8k16.row.col.f32.f16.f16.f32 "
        "{%0,%1,%2,%3}, {%4,%5,%6,%7}, {%8,%9}, {%0,%1,%2,%3};\n"
        : "+f"(c[0]), "+f"(c[1]), "+f"(c[2]), "+f"(c[3])
        : "r"(a[0]), "r"(a[1]), "r"(a[2]), "r"(a[3]),
          "r"(b0), "r"(b1));
}

__device__ __forceinline__ void cp_async16(uint32_t dst, const void* src) {
    asm volatile("cp.async.cg.shared.global [%0], [%1], 16;\n"
                 :: "r"(dst), "l"(src));
}
__device__ __forceinline__ void cp_commit() {
    asm volatile("cp.async.commit_group;\n" ::: "memory");
}
__device__ __forceinline__ void cp_wait1() {
    asm volatile("cp.async.wait_group 1;\n" ::: "memory");
}
__device__ __forceinline__ void cp_wait0() {
    asm volatile("cp.async.wait_group 0;\n" ::: "memory");
}

__device__ __forceinline__ uint32_t smem_u32(const void* p) {
    uint32_t a;
    asm("{ .reg .u64 t; cvta.to.shared.u64 t, %1; cvt.u32.u64 %0, t; }"
        : "=r"(a) : "l"(p));
    return a;
}

__device__ __forceinline__ int pp_slot(int u) {   // pair-pack slot, u in 0..7
    return 2 * (u & 3) + (u >> 2);
}

// ---------------------------------------------------------------------------
// x -> fp16 pair-pack-permuted (GEMM A operand format)
// ---------------------------------------------------------------------------
__global__ void f16perm_convert_kernel(const float* __restrict__ in,
                                       __half* __restrict__ out, int ngroups)
{
    int g = blockIdx.x * blockDim.x + threadIdx.x;
    if (g >= ngroups) return;
    const float* src = in + (size_t)g * 16;
    float f[16];
    #pragma unroll
    for (int i = 0; i < 16; i += 4)
        *(float4*)&f[i] = *(const float4*)(src + i);
    uint32_t u[8];
    #pragma unroll
    for (int s = 0; s < 8; s++) {
        const int uu = (s >> 1) + (s & 1) * 4;
        u[s] = pack_f16x2(f[2 * uu], f[2 * uu + 1]);
    }
    uint4* dst = (uint4*)(out + (size_t)g * 16);
    dst[0] = make_uint4(u[0], u[1], u[2], u[3]);
    dst[1] = make_uint4(u[4], u[5], u[6], u[7]);
}

// ---------------------------------------------------------------------------
// Weight transpose -> fp16 pair-pack-permuted [N,K] rows
// ---------------------------------------------------------------------------
__global__ void transpose_f16perm_kernel(const float* __restrict__ in,
                                         __half* __restrict__ out, int R, int C_)
{
    __shared__ float tile[32][33];
    const int c0 = blockIdx.x * 32, r0 = blockIdx.y * 32;
    const int tx = threadIdx.x, ty = threadIdx.y;
    #pragma unroll
    for (int i = 0; i < 32; i += 8)
        tile[ty + i][tx] = in[(size_t)(r0 + ty + i) * C_ + c0 + tx];
    __syncthreads();
    const int k = r0 + tx;
    const int pk = (k & ~15) + pp_slot((k >> 1) & 7) * 2 + (k & 1);
    #pragma unroll
    for (int i = 0; i < 32; i += 8)
        out[(size_t)(c0 + ty + i) * R + pk] = __float2half_rn(tile[tx][ty + i]);
}

// ---------------------------------------------------------------------------
// fp16 mma.sync GEMM. qkv_mode=1: epilogue writes transformed Q/K/V tensors.
// qkv_mode=0: plain fp32 C + bias.
// ---------------------------------------------------------------------------
#define GBM 128
#define GBK 32
#define GP64 12

__global__ __launch_bounds__(256, 2)
void gemm_f16_kernel(const __half* __restrict__ A, const __half* __restrict__ Bt,
                     const float* __restrict__ bias, float* __restrict__ C,
                     int M, int N, int K, int qkv_mode,
                     float* __restrict__ Cq, uint32_t* __restrict__ Ckh,
                     uint32_t* __restrict__ Ckl, __half* __restrict__ Cv)
{
    __shared__ __align__(16) uint2 As[2][GBM * GP64];
    __shared__ __align__(16) uint2 Bs[2][GBM * GP64];

    const int tid  = threadIdx.x;
    const int wid  = tid >> 5;
    const int lane = tid & 31;
    const int gid  = lane >> 2;
    const int tig  = lane & 3;

    const int warp_m = wid & 1;
    const int warp_n = wid >> 1;

    const int brow = blockIdx.y, bcol = blockIdx.x;
    const __half* Abase = A  + (size_t)brow * GBM * K;
    const __half* Bbase = Bt + (size_t)bcol * GBM * K;

    float acc[4][4][4];
    #pragma unroll
    for (int i = 0; i < 4; i++)
        #pragma unroll
        for (int j = 0; j < 4; j++)
            #pragma unroll
            for (int r = 0; r < 4; r++) acc[i][j][r] = 0.0f;

    auto load_tile = [&](int it, int stage) {
        const int koff = it * GBK;
        #pragma unroll
        for (int q = 0; q < 2; q++) {
            const int idx = q * 256 + tid;
            const int row = idx >> 2;
            const int grp = (idx >> 1) & 1;
            const int hf  = idx & 1;
            const int ds  = row * GP64 + grp * 4 + hf * 2;
            cp_async16(smem_u32(&As[stage][ds]),
                       Abase + (size_t)row * K + koff + grp * 16 + hf * 8);
            cp_async16(smem_u32(&Bs[stage][ds]),
                       Bbase + (size_t)row * K + koff + grp * 16 + hf * 8);
        }
    };

    const int nit = K / GBK;
    load_tile(0, 0);
    cp_commit();

    for (int it = 0; it < nit; ++it) {
        if (it + 1 < nit) {
            load_tile(it + 1, (it + 1) & 1);
            cp_commit();
            cp_wait1();
        } else {
            cp_wait0();
        }
        __syncthreads();

        const int st = it & 1;
        #pragma unroll
        for (int kk = 0; kk < 2; kk++) {
            uint32_t a[4][4];
            uint32_t b[4][2];
            #pragma unroll
            for (int i = 0; i < 4; i++) {
                const int r = warp_m * 64 + i * 16 + gid;
                const uint2 a02 = As[st][r * GP64 + kk * 4 + tig];
                const uint2 a13 = As[st][(r + 8) * GP64 + kk * 4 + tig];
                a[i][0] = a02.x; a[i][1] = a13.x;
                a[i][2] = a02.y; a[i][3] = a13.y;
            }
            #pragma unroll
            for (int j = 0; j < 4; j++) {
                const int rn = warp_n * 32 + j * 8 + gid;
                const uint2 bb = Bs[st][rn * GP64 + kk * 4 + tig];
                b[j][0] = bb.x; b[j][1] = bb.y;
            }
            #pragma unroll
            for (int i = 0; i < 4; i++)
                #pragma unroll
                for (int j = 0; j < 4; j++)
                    mma_f16(acc[i][j], a[i], b[j][0], b[j][1]);
        }
        __syncthreads();
    }

    if (!qkv_mode) {
        #pragma unroll
        for (int i = 0; i < 4; i++) {
            const int row0 = brow * GBM + warp_m * 64 + i * 16 + gid;
            #pragma unroll
            for (int j = 0; j < 4; j++) {
                const int col = bcol * GBM + warp_n * 32 + j * 8 + 2 * tig;
                const float bx = bias[col], by = bias[col + 1];
                float2 v0 = make_float2(acc[i][j][0] + bx, acc[i][j][1] + by);
                float2 v1 = make_float2(acc[i][j][2] + bx, acc[i][j][3] + by);
                *(float2*)(C + (size_t)row0 * N + col) = v0;
                *(float2*)(C + (size_t)(row0 + 8) * N + col) = v1;
            }
        }
        return;
    }

    // qkv mode: section uniform per CTA (8 bcol blocks per 1024-col section)
    const int sec = bcol >> 3;
    #pragma unroll
    for (int i = 0; i < 4; i++) {
        const int t0 = brow * GBM + warp_m * 64 + i * 16 + gid;
        #pragma unroll
        for (int j = 0; j < 4; j++) {
            const int c = bcol * GBM + warp_n * 32 + j * 8 + 2 * tig;
            const float bx = bias[c], by = bias[c + 1];
            const float a0 = acc[i][j][0] + bx, a1 = acc[i][j][1] + by;
            const float a2 = acc[i][j][2] + bx, a3 = acc[i][j][3] + by;
            const int cc = c & (CC - 1);
            const int h = cc >> 6, d = cc & 63;

            if (sec == 0) {
                // Q: prescaled fp32
                *(float2*)(Cq + (size_t)t0 * CC + cc) =
                    make_float2(a0 * SCALE_EXP2, a1 * SCALE_EXP2);
                *(float2*)(Cq + (size_t)(t0 + 8) * CC + cc) =
                    make_float2(a2 * SCALE_EXP2, a3 * SCALE_EXP2);
            } else if (sec == 1) {
                // K: bf16 hi/lo pair-packed u32 rows
                const int u = d >> 1;   // 0..31
                const int slot = ((u >> 3) << 3) + ((u & 3) << 1) + ((u & 7) >> 2);
                uint32_t h0, l0_, h1, l1_;
                split_bf16(a0, a1, h0, l0_);
                split_bf16(a2, a3, h1, l1_);
                const size_t r0o = (size_t)t0 * (CC / 2) + h * 32 + slot;
                const size_t r1o = (size_t)(t0 + 8) * (CC / 2) + h * 32 + slot;
                Ckh[r0o] = h0; Ckl[r0o] = l0_;
                Ckh[r1o] = h1; Ckl[r1o] = l1_;
            } else {
                // V: fp16, [b,tile,h][d][tk_perm]
                #pragma unroll
                for (int rr = 0; rr < 2; rr++) {
                    const int t = t0 + rr * 8;
                    const int b_ = t >> 11, tl = t & (TT - 1);
                    const int tile = tl >> 6, tk = tl & 63;
                    const int wv = tk >> 1, hf = tk & 1;
                    const int vs = ((wv >> 3) << 3) + ((wv & 3) << 1) + ((wv & 7) >> 2);
                    const int pos = 2 * vs + hf;
                    __half* vb = Cv + ((((size_t)b_ * (TT / 64) + tile) * HH + h) << 12);
                    const float va = rr ? a2 : a0;
                    const float vc = rr ? a3 : a1;
                    vb[d * 64 + pos]       = __float2half_rn(va);
                    vb[(d + 1) * 64 + pos] = __float2half_rn(vc);
                }
            }
        }
    }
}

// ---------------------------------------------------------------------------
// Flash attention: bf16 3-term S + fp16 k16 PV, all operands pre-transformed
// by the QKV GEMM epilogue. Tile loads are pure cp.async, double-buffered.
// smem: stage0 [0,30720), stage1 [30720,61440), Q staging [30720,65536).
// Stage layout (u64): KH 64x20, KL 64x20, VT 64x20 (data 16/row, pad 4).
// ---------------------------------------------------------------------------
#define APAD 68
#define KP64 20
#define STAGE_U64 (3 * 64 * KP64)         // 3840 u64 = 30720 B
#define ATTN_SMEM 65536

__global__ __launch_bounds__(256, 2)
void attn_hyb_kernel(const float* __restrict__ gq,
                     const uint32_t* __restrict__ gkh,
                     const uint32_t* __restrict__ gkl,
                     const __half* __restrict__ gv,
                     __half* __restrict__ out)
{
    extern __shared__ __align__(16) char asm_raw[];
    uint2* smu = (uint2*)asm_raw;
    float* qbuf = (float*)(asm_raw + 30720);

    const int qb = (int)gridDim.x - 1 - (int)blockIdx.x;
    const int h  = blockIdx.y;
    const int b  = blockIdx.z;
    const int q0 = qb * 128;
    const size_t bT = (size_t)b * TT;

    const int tid  = threadIdx.x;
    const int w    = tid >> 5;
    const int lane = tid & 31;
    const int gid  = lane >> 2;
    const int tig  = lane & 3;

    const int ntiles = 2 * (qb + 1);

    // Tile loader: pure cp.async, 6 x 16B per thread
    auto load_tile = [&](int t, int stage) {
        uint2* base = smu + (size_t)stage * STAGE_U64;
        const size_t kro = (bT + (size_t)t * 64) * (CC / 2) + h * 32;
        const __half* vb = gv + ((((size_t)b * (TT / 64) + t) * HH + h) << 12);
        #pragma unroll
        for (int q = 0; q < 2; q++) {
            const int idx = q * 256 + tid;       // 0..511
            const int row = idx >> 3;            // 0..63
            const int c8  = idx & 7;
            // KH
            cp_async16(smem_u32(base + row * KP64 + c8 * 2),
                       gkh + kro + (size_t)row * (CC / 2) + c8 * 4);
            // KL
            cp_async16(smem_u32(base + 64 * KP64 + row * KP64 + c8 * 2),
                       gkl + kro + (size_t)row * (CC / 2) + c8 * 4);
            // VT (row = d)
            cp_async16(smem_u32(base + 2 * 64 * KP64 + row * KP64 + c8 * 2),
                       vb + row * 64 + c8 * 8);
        }
    };

    // Issue Q copy (into qbuf) and tile-0 prefetch (stage 0, disjoint region)
    {
        #pragma unroll
        for (int q = 0; q < 8; q++) {
            const int idx = q * 256 + tid;       // 0..2047
            const int row = idx >> 4;            // 0..127
            const int c4  = idx & 15;
            cp_async16(smem_u32(qbuf + row * APAD + c4 * 4),
                       gq + (bT + q0 + row) * CC + h * DD + c4 * 4);
        }
    }
    cp_commit();
    load_tile(0, 0);
    cp_commit();

    cp_wait1();          // Q done (tile 0 may still be in flight)
    __syncthreads();

    // Extract Q bf16 hi/lo fragments (Q already prescaled)
    const int r0l = w * 16 + gid;
    const int r0g = q0 + r0l;
    uint32_t qhi[4][4], qlo[4][4];
    #pragma unroll
    for (int ks = 0; ks < 4; ks++) {
        const int d0 = ks * 16 + 2 * tig;
        float2 x0 = *(float2*)&qbuf[r0l * APAD + d0];
        float2 x1 = *(float2*)&qbuf[(r0l + 8) * APAD + d0];
        float2 x2 = *(float2*)&qbuf[r0l * APAD + d0 + 8];
        float2 x3 = *(float2*)&qbuf[(r0l + 8) * APAD + d0 + 8];
        split_bf16(x0.x, x0.y, qhi[ks][0], qlo[ks][0]);
        split_bf16(x1.x, x1.y, qhi[ks][1], qlo[ks][1]);
        split_bf16(x2.x, x2.y, qhi[ks][2], qlo[ks][2]);
        split_bf16(x3.x, x3.y, qhi[ks][3], qlo[ks][3]);
    }
    __syncthreads();     // Q region free; stage-1 prefetch may now write it

    float O[8][4];
    #pragma unroll
    for (int j = 0; j < 8; j++)
        #pragma unroll
        for (int r = 0; r < 4; r++) O[j][r] = 0.0f;
    float m0 = -1e30f, m1 = -1e30f, l0 = 0.0f, l1 = 0.0f;

    for (int t = 0; t < ntiles; t++) {
        if (t + 1 < ntiles) {
            load_tile(t + 1, (t + 1) & 1);
            cp_commit();
            cp_wait1();
        } else {
            cp_wait0();
        }
        __syncthreads();

        const uint2* KH2 = smu + (size_t)(t & 1) * STAGE_U64;
        const uint2* KL2 = KH2 + 64 * KP64;
        const uint2* VT2 = KH2 + 2 * 64 * KP64;
        const int kv0 = t * 64;

        // S = Q @ K^T (bf16 3-term)
        float s[8][4];
        #pragma unroll
        for (int j = 0; j < 8; j++)
            #pragma unroll
            for (int r = 0; r < 4; r++) s[j][r] = 0.0f;

        #pragma unroll
        for (int ks = 0; ks < 4; ks++) {
            #pragma unroll
            for (int j = 0; j < 8; j++) {
                const int pb = (j * 8 + gid) * KP64 + ks * 4 + tig;
                const uint2 bh = KH2[pb];
                const uint2 bl = KL2[pb];
                mma_bf16(s[j], qhi[ks], bh.x, bh.y);
                mma_bf16(s[j], qhi[ks], bl.x, bl.y);
                mma_bf16(s[j], qlo[ks], bh.x, bh.y);
            }
        }

        // Causal mask on the two diagonal-straddling tiles
        if (t + 2 >= ntiles) {
            #pragma unroll
            for (int j = 0; j < 8; j++) {
                const int col = kv0 + j * 8 + 2 * tig;
                if (col     > r0g)     s[j][0] = -1e30f;
                if (col + 1 > r0g)     s[j][1] = -1e30f;
                if (col     > r0g + 8) s[j][2] = -1e30f;
                if (col + 1 > r0g + 8) s[j][3] = -1e30f;
            }
        }

        // Online softmax (exp2 domain)
        float mt0 = s[0][0], mt1 = s[0][2];
        #pragma unroll
        for (int j = 0; j < 8; j++) {
            mt0 = fmaxf(mt0, fmaxf(s[j][0], s[j][1]));
            mt1 = fmaxf(mt1, fmaxf(s[j][2], s[j][3]));
        }
        mt0 = fmaxf(mt0, __shfl_xor_sync(0xffffffffu, mt0, 1));
        mt0 = fmaxf(mt0, __shfl_xor_sync(0xffffffffu, mt0, 2));
        mt1 = fmaxf(mt1, __shfl_xor_sync(0xffffffffu, mt1, 1));
        mt1 = fmaxf(mt1, __shfl_xor_sync(0xffffffffu, mt1, 2));

        const float mn0 = fmaxf(m0, mt0), mn1 = fmaxf(m1, mt1);
        const float c0 = ex2(m0 - mn0), c1 = ex2(m1 - mn1);
        l0 *= c0; l1 *= c1;
        #pragma unroll
        for (int j = 0; j < 8; j++) {
            O[j][0] *= c0; O[j][1] *= c0;
            O[j][2] *= c1; O[j][3] *= c1;
        }
        m0 = mn0; m1 = mn1;

        #pragma unroll
        for (int j = 0; j < 8; j++) {
            s[j][0] = ex2(s[j][0] - mn0);
            s[j][1] = ex2(s[j][1] - mn0);
            s[j][2] = ex2(s[j][2] - mn1);
            s[j][3] = ex2(s[j][3] - mn1);
            l0 += s[j][0] + s[j][1];
            l1 += s[j][2] + s[j][3];
        }

        // PV: fp16 k16, P packs directly into A-fragments
        #pragma unroll
        for (int jk = 0; jk < 4; jk++) {
            uint32_t a[4];
            a[0] = pack_f16x2(s[2 * jk][0],     s[2 * jk][1]);
            a[1] = pack_f16x2(s[2 * jk][2],     s[2 * jk][3]);
            a[2] = pack_f16x2(s[2 * jk + 1][0], s[2 * jk + 1][1]);
            a[3] = pack_f16x2(s[2 * jk + 1][2], s[2 * jk + 1][3]);
            #pragma unroll
            for (int jo = 0; jo < 8; jo++) {
                const uint2 vv = VT2[(jo * 8 + gid) * KP64 + jk * 4 + tig];
                mma_f16(O[jo], a, vv.x, vv.y);
            }
        }
        __syncthreads();
    }

    // Finalize: write fp16 pair-pack-permuted rows into g_att16
    l0 += __shfl_xor_sync(0xffffffffu, l0, 1);
    l0 += __shfl_xor_sync(0xffffffffu, l0, 2);
    l1 += __shfl_xor_sync(0xffffffffu, l1, 1);
    l1 += __shfl_xor_sync(0xffffffffu, l1, 2);
    const float i0 = 1.0f / l0, i1 = 1.0f / l1;

    __half* ob = out + (bT + r0g) * CC + h * DD;
    #pragma unroll
    for (int j = 0; j < 8; j++) {
        const int off = ((j >> 1) << 4) + ((2 * tig + (j & 1)) << 1);
        *(uint32_t*)(ob + off) =
            pack_f16x2(O[j][0] * i0, O[j][1] * i0);
        *(uint32_t*)(ob + (size_t)8 * CC + off) =
            pack_f16x2(O[j][2] * i1, O[j][3] * i1);
    }
}

// ---------------------------------------------------------------------------
// Launch
// ---------------------------------------------------------------------------
extern "C" void kernel_launch(void* const* d_in, const int* in_sizes, int n_in,
                              void* d_out, int out_size)
{
    const float* x     = (const float*)d_in[0];
    const float* w_qkv = (const float*)d_in[1];
    const float* b_qkv = (const float*)d_in[2];
    const float* w_out = (const float*)d_in[3];
    const float* b_out = (const float*)d_in[4];
    float* out = (float*)d_out;

    float*    gq = nullptr;    cudaGetSymbolAddress((void**)&gq, g_q);
    uint32_t* gkh = nullptr;   cudaGetSymbolAddress((void**)&gkh, g_kh);
    uint32_t* gkl = nullptr;   cudaGetSymbolAddress((void**)&gkl, g_kl);
    __half*   gv = nullptr;    cudaGetSymbolAddress((void**)&gv, g_v16);
    __half*   att16 = nullptr; cudaGetSymbolAddress((void**)&att16, g_att16);
    __half*   x16 = nullptr;   cudaGetSymbolAddress((void**)&x16, g_x16);
    __half*   wqkvT = nullptr; cudaGetSymbolAddress((void**)&wqkvT, g_wqkvT16);
    __half*   woutT = nullptr; cudaGetSymbolAddress((void**)&woutT, g_woutT16);

    cudaFuncSetAttribute(attn_hyb_kernel,
                         cudaFuncAttributeMaxDynamicSharedMemorySize, ATTN_SMEM);

    // Preproc: x -> fp16 perm; weights -> transposed fp16 perm
    {
        const int ngroups = MM * CC / 16;
        f16perm_convert_kernel<<<ngroups / 256, 256>>>(x, x16, ngroups);
        dim3 blk(32, 8);
        transpose_f16perm_kernel<<<dim3((3 * CC) / 32, CC / 32), blk>>>(w_qkv, wqkvT, CC, 3 * CC);
        transpose_f16perm_kernel<<<dim3(CC / 32, CC / 32), blk>>>(w_out, woutT, CC, CC);
    }

    // QKV projection (fp16 mma) with fused Q/K/V transformation
    {
        dim3 grid((3 * CC) / 128, MM / 128);
        gemm_f16_kernel<<<grid, 256>>>(x16, wqkvT, b_qkv, nullptr,
                                       MM, 3 * CC, CC, 1, gq, gkh, gkl, gv);
    }

    // Flash attention (bf16-S / fp16-PV, cp.async double-buffered)
    {
        dim3 grid(TT / 128, HH, BB);
        attn_hyb_kernel<<<grid, 256, ATTN_SMEM>>>(gq, gkh, gkl, gv, att16);
    }

    // Output projection (fp16 mma, plain epilogue)
    {
        dim3 grid(CC / 128, MM / 128);
        gemm_f16_kernel<<<grid, 256>>>(att16, woutT, b_out, out,
                                       MM, CC, CC, 0,
                                       nullptr, nullptr, nullptr, nullptr);
    }
}

// round 13
// speedup vs baseline: 3.7837x; 1.1431x over previous
#include <cuda_runtime.h>
#include <cuda_bf16.h>
#include <cuda_fp16.h>
#include <cstdint>

// Problem constants
#define BB 4
#define TT 2048
#define CC 1024
#define HH 16
#define DD 64
#define MM (BB*TT)        // 8192

#define SCALE_EXP2 0.1803368801111204f   // 0.125 * log2(e)

// Scratch (device globals: allocation-free rule)
__device__ uint32_t g_q16[(size_t)MM * CC / 2];  // fp16 pair-packed prescaled Q
__device__ uint32_t g_kh[(size_t)MM * CC / 2];   // fp16-hi pair-packed K
__device__ uint32_t g_kl[(size_t)MM * CC / 2];   // fp16-lo (residual) pair-packed K
__device__ __half   g_v16[(size_t)MM * CC];      // fp16 V, [b,tile,h][d][tk_perm]
__device__ __half   g_att16[(size_t)MM * CC];    // attention out, fp16 perm
__device__ __half   g_x16[(size_t)MM * CC];      // fp16 perm x
__device__ __half   g_wqkvT16[(size_t)3 * CC * CC];
__device__ __half   g_woutT16[(size_t)CC * CC];

// ---------------------------------------------------------------------------
// Helpers
// ---------------------------------------------------------------------------
__device__ __forceinline__ float ex2(float x) {
    float y;
    asm("ex2.approx.ftz.f32 %0, %1;" : "=f"(y) : "f"(x));
    return y;
}

__device__ __forceinline__ uint32_t pack_f16x2(float x, float y) {
    uint32_t r;
    asm("cvt.rn.f16x2.f32 %0, %1, %2;" : "=r"(r) : "f"(y), "f"(x));
    return r;
}

// split float pair into f16x2 hi + f16x2 residual
__device__ __forceinline__ void split_f16(float x, float y,
                                          uint32_t& hi, uint32_t& lo) {
    __half hx = __float2half_rn(x);
    __half hy = __float2half_rn(y);
    float rx = x - __half2float(hx);
    float ry = y - __half2float(hy);
    hi = pack_f16x2(__half2float(hx), __half2float(hy));
    lo = pack_f16x2(rx, ry);
}

// m16n8k16 f16 mma, fp32 accumulate
__device__ __forceinline__ void mma_f16(float* c, const uint32_t* a,
                                        uint32_t b0, uint32_t b1) {
    asm volatile(
        "mma.sync.aligned.m16n8k16.row.col.f32.f16.f16.f32 "
        "{%0,%1,%2,%3}, {%4,%5,%6,%7}, {%8,%9}, {%0,%1,%2,%3};\n"
        : "+f"(c[0]), "+f"(c[1]), "+f"(c[2]), "+f"(c[3])
        : "r"(a[0]), "r"(a[1]), "r"(a[2]), "r"(a[3]),
          "r"(b0), "r"(b1));
}

__device__ __forceinline__ void cp_async16(uint32_t dst, const void* src) {
    asm volatile("cp.async.cg.shared.global [%0], [%1], 16;\n"
                 :: "r"(dst), "l"(src));
}
__device__ __forceinline__ void cp_commit() {
    asm volatile("cp.async.commit_group;\n" ::: "memory");
}
__device__ __forceinline__ void cp_wait1() {
    asm volatile("cp.async.wait_group 1;\n" ::: "memory");
}
__device__ __forceinline__ void cp_wait0() {
    asm volatile("cp.async.wait_group 0;\n" ::: "memory");
}

__device__ __forceinline__ uint32_t smem_u32(const void* p) {
    uint32_t a;
    asm("{ .reg .u64 t; cvta.to.shared.u64 t, %1; cvt.u32.u64 %0, t; }"
        : "=r"(a) : "l"(p));
    return a;
}

__device__ __forceinline__ int pp_slot(int u) {   // pair-pack slot, u in 0..7
    return 2 * (u & 3) + (u >> 2);
}

// ---------------------------------------------------------------------------
// x -> fp16 pair-pack-permuted (GEMM A operand format)
// ---------------------------------------------------------------------------
__global__ void f16perm_convert_kernel(const float* __restrict__ in,
                                       __half* __restrict__ out, int ngroups)
{
    int g = blockIdx.x * blockDim.x + threadIdx.x;
    if (g >= ngroups) return;
    const float* src = in + (size_t)g * 16;
    float f[16];
    #pragma unroll
    for (int i = 0; i < 16; i += 4)
        *(float4*)&f[i] = *(const float4*)(src + i);
    uint32_t u[8];
    #pragma unroll
    for (int s = 0; s < 8; s++) {
        const int uu = (s >> 1) + (s & 1) * 4;
        u[s] = pack_f16x2(f[2 * uu], f[2 * uu + 1]);
    }
    uint4* dst = (uint4*)(out + (size_t)g * 16);
    dst[0] = make_uint4(u[0], u[1], u[2], u[3]);
    dst[1] = make_uint4(u[4], u[5], u[6], u[7]);
}

// ---------------------------------------------------------------------------
// Weight transpose -> fp16 pair-pack-permuted [N,K] rows
// ---------------------------------------------------------------------------
__global__ void transpose_f16perm_kernel(const float* __restrict__ in,
                                         __half* __restrict__ out, int R, int C_)
{
    __shared__ float tile[32][33];
    const int c0 = blockIdx.x * 32, r0 = blockIdx.y * 32;
    const int tx = threadIdx.x, ty = threadIdx.y;
    #pragma unroll
    for (int i = 0; i < 32; i += 8)
        tile[ty + i][tx] = in[(size_t)(r0 + ty + i) * C_ + c0 + tx];
    __syncthreads();
    const int k = r0 + tx;
    const int pk = (k & ~15) + pp_slot((k >> 1) & 7) * 2 + (k & 1);
    #pragma unroll
    for (int i = 0; i < 32; i += 8)
        out[(size_t)(c0 + ty + i) * R + pk] = __float2half_rn(tile[tx][ty + i]);
}

// ---------------------------------------------------------------------------
// fp16 mma.sync GEMM, BK=64 (16 iterations for K=1024).
// smem: As 2 stages x 128 rows x pitch 20 u64, then Bs same. 81,920 B dynamic.
// qkv_mode=1: epilogue writes transformed Q(fp16 perm)/K(hi,lo)/V tensors.
// ---------------------------------------------------------------------------
#define GBM 128
#define GBK 64
#define GPIT 20                       // u64 pitch per row (16 data + 4 pad)
#define GSTG (GBM * GPIT)             // u64 per stage per matrix (2560)
#define GEMM_SMEM (4 * GSTG * 8)      // 81,920 B

__global__ __launch_bounds__(256, 2)
void gemm_f16_kernel(const __half* __restrict__ A, const __half* __restrict__ Bt,
                     const float* __restrict__ bias, float* __restrict__ C,
                     int M, int N, int K, int qkv_mode,
                     uint32_t* __restrict__ Cq, uint32_t* __restrict__ Ckh,
                     uint32_t* __restrict__ Ckl, __half* __restrict__ Cv)
{
    extern __shared__ __align__(16) char gsm_raw[];
    uint2* As64 = (uint2*)gsm_raw;            // stages 0,1
    uint2* Bs64 = As64 + 2 * GSTG;            // stages 0,1

    const int tid  = threadIdx.x;
    const int wid  = tid >> 5;
    const int lane = tid & 31;
    const int gid  = lane >> 2;
    const int tig  = lane & 3;

    const int warp_m = wid & 1;
    const int warp_n = wid >> 1;

    const int brow = blockIdx.y, bcol = blockIdx.x;
    const __half* Abase = A  + (size_t)brow * GBM * K;
    const __half* Bbase = Bt + (size_t)bcol * GBM * K;

    float acc[4][4][4];
    #pragma unroll
    for (int i = 0; i < 4; i++)
        #pragma unroll
        for (int j = 0; j < 4; j++)
            #pragma unroll
            for (int r = 0; r < 4; r++) acc[i][j][r] = 0.0f;

    auto load_tile = [&](int it, int stage) {
        const int koff = it * GBK;
        #pragma unroll
        for (int q = 0; q < 4; q++) {
            const int idx = q * 256 + tid;   // 0..1023
            const int row = idx >> 3;        // 0..127
            const int c8  = idx & 7;
            const int ds  = stage * GSTG + row * GPIT + c8 * 2;
            cp_async16(smem_u32(As64 + ds),
                       Abase + (size_t)row * K + koff + c8 * 8);
            cp_async16(smem_u32(Bs64 + ds),
                       Bbase + (size_t)row * K + koff + c8 * 8);
        }
    };

    const int nit = K / GBK;
    load_tile(0, 0);
    cp_commit();

    for (int it = 0; it < nit; ++it) {
        if (it + 1 < nit) {
            load_tile(it + 1, (it + 1) & 1);
            cp_commit();
            cp_wait1();
        } else {
            cp_wait0();
        }
        __syncthreads();

        const uint2* As_ = As64 + (it & 1) * GSTG;
        const uint2* Bs_ = Bs64 + (it & 1) * GSTG;
        #pragma unroll
        for (int kk = 0; kk < 4; kk++) {
            uint32_t a[4][4];
            uint32_t b[4][2];
            #pragma unroll
            for (int i = 0; i < 4; i++) {
                const int r = warp_m * 64 + i * 16 + gid;
                const uint2 a02 = As_[r * GPIT + kk * 4 + tig];
                const uint2 a13 = As_[(r + 8) * GPIT + kk * 4 + tig];
                a[i][0] = a02.x; a[i][1] = a13.x;
                a[i][2] = a02.y; a[i][3] = a13.y;
            }
            #pragma unroll
            for (int j = 0; j < 4; j++) {
                const int rn = warp_n * 32 + j * 8 + gid;
                const uint2 bb = Bs_[rn * GPIT + kk * 4 + tig];
                b[j][0] = bb.x; b[j][1] = bb.y;
            }
            #pragma unroll
            for (int i = 0; i < 4; i++)
                #pragma unroll
                for (int j = 0; j < 4; j++)
                    mma_f16(acc[i][j], a[i], b[j][0], b[j][1]);
        }
        __syncthreads();
    }

    if (!qkv_mode) {
        #pragma unroll
        for (int i = 0; i < 4; i++) {
            const int row0 = brow * GBM + warp_m * 64 + i * 16 + gid;
            #pragma unroll
            for (int j = 0; j < 4; j++) {
                const int col = bcol * GBM + warp_n * 32 + j * 8 + 2 * tig;
                const float bx = bias[col], by = bias[col + 1];
                float2 v0 = make_float2(acc[i][j][0] + bx, acc[i][j][1] + by);
                float2 v1 = make_float2(acc[i][j][2] + bx, acc[i][j][3] + by);
                *(float2*)(C + (size_t)row0 * N + col) = v0;
                *(float2*)(C + (size_t)(row0 + 8) * N + col) = v1;
            }
        }
        return;
    }

    // qkv mode: section uniform per CTA (8 bcol blocks per 1024-col section)
    const int sec = bcol >> 3;
    #pragma unroll
    for (int i = 0; i < 4; i++) {
        const int t0 = brow * GBM + warp_m * 64 + i * 16 + gid;
        #pragma unroll
        for (int j = 0; j < 4; j++) {
            const int c = bcol * GBM + warp_n * 32 + j * 8 + 2 * tig;
            const float bx = bias[c], by = bias[c + 1];
            const float a0 = acc[i][j][0] + bx, a1 = acc[i][j][1] + by;
            const float a2 = acc[i][j][2] + bx, a3 = acc[i][j][3] + by;
            const int cc = c & (CC - 1);
            const int h = cc >> 6, d = cc & 63;
            const int u = d >> 1;   // 0..31
            const int slot = ((u >> 3) << 3) + ((u & 3) << 1) + ((u & 7) >> 2);

            if (sec == 0) {
                // Q: fp16 pair-packed, prescaled into exp2 domain
                const size_t r0o = (size_t)t0 * (CC / 2) + h * 32 + slot;
                const size_t r1o = (size_t)(t0 + 8) * (CC / 2) + h * 32 + slot;
                Cq[r0o] = pack_f16x2(a0 * SCALE_EXP2, a1 * SCALE_EXP2);
                Cq[r1o] = pack_f16x2(a2 * SCALE_EXP2, a3 * SCALE_EXP2);
            } else if (sec == 1) {
                // K: fp16 hi/lo pair-packed u32 rows
                uint32_t h0, l0_, h1, l1_;
                split_f16(a0, a1, h0, l0_);
                split_f16(a2, a3, h1, l1_);
                const size_t r0o = (size_t)t0 * (CC / 2) + h * 32 + slot;
                const size_t r1o = (size_t)(t0 + 8) * (CC / 2) + h * 32 + slot;
                Ckh[r0o] = h0; Ckl[r0o] = l0_;
                Ckh[r1o] = h1; Ckl[r1o] = l1_;
            } else {
                // V: fp16, [b,tile,h][d][tk_perm]
                #pragma unroll
                for (int rr = 0; rr < 2; rr++) {
                    const int t = t0 + rr * 8;
                    const int b_ = t >> 11, tl = t & (TT - 1);
                    const int tile = tl >> 6, tk = tl & 63;
                    const int wv = tk >> 1, hf = tk & 1;
                    const int vs = ((wv >> 3) << 3) + ((wv & 3) << 1) + ((wv & 7) >> 2);
                    const int pos = 2 * vs + hf;
                    __half* vb = Cv + ((((size_t)b_ * (TT / 64) + tile) * HH + h) << 12);
                    const float va = rr ? a2 : a0;
                    const float vc = rr ? a3 : a1;
                    vb[d * 64 + pos]       = __float2half_rn(va);
                    vb[(d + 1) * 64 + pos] = __float2half_rn(vc);
                }
            }
        }
    }
}

// ---------------------------------------------------------------------------
// Flash attention: fp16 2-term S (q_f16 * (k_hi + k_lo)) + fp16 k16 PV.
// All operands pre-transformed by the QKV GEMM epilogue; loads pure cp.async.
// smem (u64 units): stage0 [0,3840), stage1 [3840,7680), Q [7680,10240).
// Stage layout: KH 64x20, KL 64x20, VT 64x20. Q: 128 rows x pitch 20.
// ---------------------------------------------------------------------------
#define KP64 20
#define STAGE_U64 (3 * 64 * KP64)         // 3840 u64 = 30,720 B
#define ATTN_SMEM ((2 * STAGE_U64 + 128 * KP64) * 8)   // 81,920 B

__global__ __launch_bounds__(256, 2)
void attn_hyb_kernel(const uint32_t* __restrict__ gq,
                     const uint32_t* __restrict__ gkh,
                     const uint32_t* __restrict__ gkl,
                     const __half* __restrict__ gv,
                     __half* __restrict__ out)
{
    extern __shared__ __align__(16) char asm_raw[];
    uint2* smu  = (uint2*)asm_raw;
    uint2* qbuf = smu + 2 * STAGE_U64;

    const int qb = (int)gridDim.x - 1 - (int)blockIdx.x;
    const int h  = blockIdx.y;
    const int b  = blockIdx.z;
    const int q0 = qb * 128;
    const size_t bT = (size_t)b * TT;

    const int tid  = threadIdx.x;
    const int w    = tid >> 5;
    const int lane = tid & 31;
    const int gid  = lane >> 2;
    const int tig  = lane & 3;

    const int ntiles = 2 * (qb + 1);

    // Tile loader: pure cp.async, 6 x 16B per thread
    auto load_tile = [&](int t, int stage) {
        uint2* base = smu + (size_t)stage * STAGE_U64;
        const size_t kro = (bT + (size_t)t * 64) * (CC / 2) + h * 32;
        const __half* vb = gv + ((((size_t)b * (TT / 64) + t) * HH + h) << 12);
        #pragma unroll
        for (int q = 0; q < 2; q++) {
            const int idx = q * 256 + tid;       // 0..511
            const int row = idx >> 3;            // 0..63
            const int c8  = idx & 7;
            cp_async16(smem_u32(base + row * KP64 + c8 * 2),
                       gkh + kro + (size_t)row * (CC / 2) + c8 * 4);
            cp_async16(smem_u32(base + 64 * KP64 + row * KP64 + c8 * 2),
                       gkl + kro + (size_t)row * (CC / 2) + c8 * 4);
            cp_async16(smem_u32(base + 2 * 64 * KP64 + row * KP64 + c8 * 2),
                       vb + row * 64 + c8 * 8);
        }
    };

    // Prologue: Q copy (group 0), tile-0 prefetch (group 1).
    // FIXED: 128 rows x 8 chunks of 16B each (32 u32 per row), contiguous.
    {
        const size_t qro = (bT + q0) * (CC / 2) + h * 32;
        #pragma unroll
        for (int q = 0; q < 4; q++) {
            const int idx = q * 256 + tid;       // 0..1023
            const int row = idx >> 3;            // 0..127
            const int c8  = idx & 7;             // 8 x 16B per 128B row
            cp_async16(smem_u32(qbuf + row * KP64 + c8 * 2),
                       gq + qro + (size_t)row * (CC / 2) + c8 * 4);
        }
    }
    cp_commit();
    load_tile(0, 0);
    cp_commit();

    cp_wait1();          // Q done (tile 0 may still be in flight)
    __syncthreads();

    // Extract Q fp16 A-fragments (already prescaled + permuted)
    const int r0l = w * 16 + gid;
    const int r0g = q0 + r0l;
    uint32_t qf[4][4];
    #pragma unroll
    for (int ks = 0; ks < 4; ks++) {
        const uint2 a02 = qbuf[r0l * KP64 + ks * 4 + tig];
        const uint2 a13 = qbuf[(r0l + 8) * KP64 + ks * 4 + tig];
        qf[ks][0] = a02.x; qf[ks][1] = a13.x;
        qf[ks][2] = a02.y; qf[ks][3] = a13.y;
    }

    float O[8][4];
    #pragma unroll
    for (int j = 0; j < 8; j++)
        #pragma unroll
        for (int r = 0; r < 4; r++) O[j][r] = 0.0f;
    float m0 = -1e30f, m1 = -1e30f, l0 = 0.0f, l1 = 0.0f;

    for (int t = 0; t < ntiles; t++) {
        if (t + 1 < ntiles) {
            load_tile(t + 1, (t + 1) & 1);
            cp_commit();
            cp_wait1();
        } else {
            cp_wait0();
        }
        __syncthreads();

        const uint2* KH2 = smu + (size_t)(t & 1) * STAGE_U64;
        const uint2* KL2 = KH2 + 64 * KP64;
        const uint2* VT2 = KH2 + 2 * 64 * KP64;
        const int kv0 = t * 64;

        // S = Q @ K^T (fp16 2-term: q*khi + q*klo)
        float s[8][4];
        #pragma unroll
        for (int j = 0; j < 8; j++)
            #pragma unroll
            for (int r = 0; r < 4; r++) s[j][r] = 0.0f;

        #pragma unroll
        for (int ks = 0; ks < 4; ks++) {
            #pragma unroll
            for (int j = 0; j < 8; j++) {
                const int pb = (j * 8 + gid) * KP64 + ks * 4 + tig;
                const uint2 bh = KH2[pb];
                const uint2 bl = KL2[pb];
                mma_f16(s[j], qf[ks], bh.x, bh.y);
                mma_f16(s[j], qf[ks], bl.x, bl.y);
            }
        }

        // Causal mask on the two diagonal-straddling tiles
        if (t + 2 >= ntiles) {
            #pragma unroll
            for (int j = 0; j < 8; j++) {
                const int col = kv0 + j * 8 + 2 * tig;
                if (col     > r0g)     s[j][0] = -1e30f;
                if (col + 1 > r0g)     s[j][1] = -1e30f;
                if (col     > r0g + 8) s[j][2] = -1e30f;
                if (col + 1 > r0g + 8) s[j][3] = -1e30f;
            }
        }

        // Online softmax (exp2 domain)
        float mt0 = s[0][0], mt1 = s[0][2];
        #pragma unroll
        for (int j = 0; j < 8; j++) {
            mt0 = fmaxf(mt0, fmaxf(s[j][0], s[j][1]));
            mt1 = fmaxf(mt1, fmaxf(s[j][2], s[j][3]));
        }
        mt0 = fmaxf(mt0, __shfl_xor_sync(0xffffffffu, mt0, 1));
        mt0 = fmaxf(mt0, __shfl_xor_sync(0xffffffffu, mt0, 2));
        mt1 = fmaxf(mt1, __shfl_xor_sync(0xffffffffu, mt1, 1));
        mt1 = fmaxf(mt1, __shfl_xor_sync(0xffffffffu, mt1, 2));

        const float mn0 = fmaxf(m0, mt0), mn1 = fmaxf(m1, mt1);
        const float c0 = ex2(m0 - mn0), c1 = ex2(m1 - mn1);
        l0 *= c0; l1 *= c1;
        #pragma unroll
        for (int j = 0; j < 8; j++) {
            O[j][0] *= c0; O[j][1] *= c0;
            O[j][2] *= c1; O[j][3] *= c1;
        }
        m0 = mn0; m1 = mn1;

        #pragma unroll
        for (int j = 0; j < 8; j++) {
            s[j][0] = ex2(s[j][0] - mn0);
            s[j][1] = ex2(s[j][1] - mn0);
            s[j][2] = ex2(s[j][2] - mn1);
            s[j][3] = ex2(s[j][3] - mn1);
            l0 += s[j][0] + s[j][1];
            l1 += s[j][2] + s[j][3];
        }

        // PV: fp16 k16, P packs directly into A-fragments
        #pragma unroll
        for (int jk = 0; jk < 4; jk++) {
            uint32_t a[4];
            a[0] = pack_f16x2(s[2 * jk][0],     s[2 * jk][1]);
            a[1] = pack_f16x2(s[2 * jk][2],     s[2 * jk][3]);
            a[2] = pack_f16x2(s[2 * jk + 1][0], s[2 * jk + 1][1]);
            a[3] = pack_f16x2(s[2 * jk + 1][2], s[2 * jk + 1][3]);
            #pragma unroll
            for (int jo = 0; jo < 8; jo++) {
                const uint2 vv = VT2[(jo * 8 + gid) * KP64 + jk * 4 + tig];
                mma_f16(O[jo], a, vv.x, vv.y);
            }
        }
        __syncthreads();
    }

    // Finalize: write fp16 pair-pack-permuted rows into g_att16
    l0 += __shfl_xor_sync(0xffffffffu, l0, 1);
    l0 += __shfl_xor_sync(0xffffffffu, l0, 2);
    l1 += __shfl_xor_sync(0xffffffffu, l1, 1);
    l1 += __shfl_xor_sync(0xffffffffu, l1, 2);
    const float i0 = 1.0f / l0, i1 = 1.0f / l1;

    __half* ob = out + (bT + r0g) * CC + h * DD;
    #pragma unroll
    for (int j = 0; j < 8; j++) {
        const int off = ((j >> 1) << 4) + ((2 * tig + (j & 1)) << 1);
        *(uint32_t*)(ob + off) =
            pack_f16x2(O[j][0] * i0, O[j][1] * i0);
        *(uint32_t*)(ob + (size_t)8 * CC + off) =
            pack_f16x2(O[j][2] * i1, O[j][3] * i1);
    }
}

// ---------------------------------------------------------------------------
// Launch
// ---------------------------------------------------------------------------
extern "C" void kernel_launch(void* const* d_in, const int* in_sizes, int n_in,
                              void* d_out, int out_size)
{
    const float* x     = (const float*)d_in[0];
    const float* w_qkv = (const float*)d_in[1];
    const float* b_qkv = (const float*)d_in[2];
    const float* w_out = (const float*)d_in[3];
    const float* b_out = (const float*)d_in[4];
    float* out = (float*)d_out;

    uint32_t* gq = nullptr;    cudaGetSymbolAddress((void**)&gq, g_q16);
    uint32_t* gkh = nullptr;   cudaGetSymbolAddress((void**)&gkh, g_kh);
    uint32_t* gkl = nullptr;   cudaGetSymbolAddress((void**)&gkl, g_kl);
    __half*   gv = nullptr;    cudaGetSymbolAddress((void**)&gv, g_v16);
    __half*   att16 = nullptr; cudaGetSymbolAddress((void**)&att16, g_att16);
    __half*   x16 = nullptr;   cudaGetSymbolAddress((void**)&x16, g_x16);
    __half*   wqkvT = nullptr; cudaGetSymbolAddress((void**)&wqkvT, g_wqkvT16);
    __half*   woutT = nullptr; cudaGetSymbolAddress((void**)&woutT, g_woutT16);

    cudaFuncSetAttribute(gemm_f16_kernel,
                         cudaFuncAttributeMaxDynamicSharedMemorySize, GEMM_SMEM);
    cudaFuncSetAttribute(attn_hyb_kernel,
                         cudaFuncAttributeMaxDynamicSharedMemorySize, ATTN_SMEM);

    // Preproc: x -> fp16 perm; weights -> transposed fp16 perm
    {
        const int ngroups = MM * CC / 16;
        f16perm_convert_kernel<<<ngroups / 256, 256>>>(x, x16, ngroups);
        dim3 blk(32, 8);
        transpose_f16perm_kernel<<<dim3((3 * CC) / 32, CC / 32), blk>>>(w_qkv, wqkvT, CC, 3 * CC);
        transpose_f16perm_kernel<<<dim3(CC / 32, CC / 32), blk>>>(w_out, woutT, CC, CC);
    }

    // QKV projection (fp16 mma, BK=64) with fused Q/K/V transformation
    {
        dim3 grid((3 * CC) / 128, MM / 128);
        gemm_f16_kernel<<<grid, 256, GEMM_SMEM>>>(x16, wqkvT, b_qkv, nullptr,
                                                  MM, 3 * CC, CC, 1,
                                                  gq, gkh, gkl, gv);
    }

    // Flash attention (fp16 2-term S / fp16 PV, cp.async double-buffered)
    {
        dim3 grid(TT / 128, HH, BB);
        attn_hyb_kernel<<<grid, 256, ATTN_SMEM>>>(gq, gkh, gkl, gv, att16);
    }

    // Output projection (fp16 mma, BK=64, plain epilogue)
    {
        dim3 grid(CC / 128, MM / 128);
        gemm_f16_kernel<<<grid, 256, GEMM_SMEM>>>(att16, woutT, b_out, out,
                                                  MM, CC, CC, 0,
                                                  nullptr, nullptr, nullptr, nullptr);
    }
}

// round 14
// speedup vs baseline: 4.3371x; 1.1463x over previous
#include <cuda_runtime.h>
#include <cuda_bf16.h>
#include <cuda_fp16.h>
#include <cstdint>

// Problem constants
#define BB 4
#define TT 2048
#define CC 1024
#define HH 16
#define DD 64
#define MM (BB*TT)        // 8192

#define SCALE_EXP2 0.1803368801111204f   // 0.125 * log2(e)

// Scratch (device globals: allocation-free rule)
__device__ uint32_t g_q16[(size_t)MM * CC / 2];  // fp16 pair-packed prescaled Q
__device__ uint32_t g_k16[(size_t)MM * CC / 2];  // fp16 pair-packed K
__device__ __half   g_v16[(size_t)MM * CC];      // fp16 V, [b,tile,h][d][tk_perm]
__device__ __half   g_att16[(size_t)MM * CC];    // attention out, fp16 perm
__device__ __half   g_x16[(size_t)MM * CC];      // fp16 perm x
__device__ __half   g_wqkvT16[(size_t)3 * CC * CC];
__device__ __half   g_woutT16[(size_t)CC * CC];

// ---------------------------------------------------------------------------
// Helpers
// ---------------------------------------------------------------------------
__device__ __forceinline__ float ex2(float x) {
    float y;
    asm("ex2.approx.ftz.f32 %0, %1;" : "=f"(y) : "f"(x));
    return y;
}

__device__ __forceinline__ uint32_t pack_f16x2(float x, float y) {
    uint32_t r;
    asm("cvt.rn.f16x2.f32 %0, %1, %2;" : "=r"(r) : "f"(y), "f"(x));
    return r;
}

// m16n8k16 f16 mma, fp32 accumulate
__device__ __forceinline__ void mma_f16(float* c, const uint32_t* a,
                                        uint32_t b0, uint32_t b1) {
    asm volatile(
        "mma.sync.aligned.m16n8k16.row.col.f32.f16.f16.f32 "
        "{%0,%1,%2,%3}, {%4,%5,%6,%7}, {%8,%9}, {%0,%1,%2,%3};\n"
        : "+f"(c[0]), "+f"(c[1]), "+f"(c[2]), "+f"(c[3])
        : "r"(a[0]), "r"(a[1]), "r"(a[2]), "r"(a[3]),
          "r"(b0), "r"(b1));
}

__device__ __forceinline__ void cp_async16(uint32_t dst, const void* src) {
    asm volatile("cp.async.cg.shared.global [%0], [%1], 16;\n"
                 :: "r"(dst), "l"(src));
}
__device__ __forceinline__ void cp_commit() {
    asm volatile("cp.async.commit_group;\n" ::: "memory");
}
__device__ __forceinline__ void cp_wait1() {
    asm volatile("cp.async.wait_group 1;\n" ::: "memory");
}
__device__ __forceinline__ void cp_wait0() {
    asm volatile("cp.async.wait_group 0;\n" ::: "memory");
}

__device__ __forceinline__ uint32_t smem_u32(const void* p) {
    uint32_t a;
    asm("{ .reg .u64 t; cvta.to.shared.u64 t, %1; cvt.u32.u64 %0, t; }"
        : "=r"(a) : "l"(p));
    return a;
}

__device__ __forceinline__ int pp_slot(int u) {   // pair-pack slot, u in 0..7
    return 2 * (u & 3) + (u >> 2);
}

// ---------------------------------------------------------------------------
// x -> fp16 pair-pack-permuted (GEMM A operand format)
// ---------------------------------------------------------------------------
__global__ void f16perm_convert_kernel(const float* __restrict__ in,
                                       __half* __restrict__ out, int ngroups)
{
    int g = blockIdx.x * blockDim.x + threadIdx.x;
    if (g >= ngroups) return;
    const float* src = in + (size_t)g * 16;
    float f[16];
    #pragma unroll
    for (int i = 0; i < 16; i += 4)
        *(float4*)&f[i] = *(const float4*)(src + i);
    uint32_t u[8];
    #pragma unroll
    for (int s = 0; s < 8; s++) {
        const int uu = (s >> 1) + (s & 1) * 4;
        u[s] = pack_f16x2(f[2 * uu], f[2 * uu + 1]);
    }
    uint4* dst = (uint4*)(out + (size_t)g * 16);
    dst[0] = make_uint4(u[0], u[1], u[2], u[3]);
    dst[1] = make_uint4(u[4], u[5], u[6], u[7]);
}

// ---------------------------------------------------------------------------
// Weight transpose -> fp16 pair-pack-permuted [N,K] rows
// ---------------------------------------------------------------------------
__global__ void transpose_f16perm_kernel(const float* __restrict__ in,
                                         __half* __restrict__ out, int R, int C_)
{
    __shared__ float tile[32][33];
    const int c0 = blockIdx.x * 32, r0 = blockIdx.y * 32;
    const int tx = threadIdx.x, ty = threadIdx.y;
    #pragma unroll
    for (int i = 0; i < 32; i += 8)
        tile[ty + i][tx] = in[(size_t)(r0 + ty + i) * C_ + c0 + tx];
    __syncthreads();
    const int k = r0 + tx;
    const int pk = (k & ~15) + pp_slot((k >> 1) & 7) * 2 + (k & 1);
    #pragma unroll
    for (int i = 0; i < 32; i += 8)
        out[(size_t)(c0 + ty + i) * R + pk] = __float2half_rn(tile[tx][ty + i]);
}

// ---------------------------------------------------------------------------
// fp16 mma.sync GEMM, BK=64 (16 iterations for K=1024).
// qkv_mode=1: epilogue writes transformed Q/K (fp16 perm) and V tensors.
// ---------------------------------------------------------------------------
#define GBM 128
#define GBK 64
#define GPIT 20                       // u64 pitch per row (16 data + 4 pad)
#define GSTG (GBM * GPIT)             // u64 per stage per matrix (2560)
#define GEMM_SMEM (4 * GSTG * 8)      // 81,920 B

__global__ __launch_bounds__(256, 2)
void gemm_f16_kernel(const __half* __restrict__ A, const __half* __restrict__ Bt,
                     const float* __restrict__ bias, float* __restrict__ C,
                     int M, int N, int K, int qkv_mode,
                     uint32_t* __restrict__ Cq, uint32_t* __restrict__ Ck,
                     __half* __restrict__ Cv)
{
    extern __shared__ __align__(16) char gsm_raw[];
    uint2* As64 = (uint2*)gsm_raw;            // stages 0,1
    uint2* Bs64 = As64 + 2 * GSTG;            // stages 0,1

    const int tid  = threadIdx.x;
    const int wid  = tid >> 5;
    const int lane = tid & 31;
    const int gid  = lane >> 2;
    const int tig  = lane & 3;

    const int warp_m = wid & 1;
    const int warp_n = wid >> 1;

    const int brow = blockIdx.y, bcol = blockIdx.x;
    const __half* Abase = A  + (size_t)brow * GBM * K;
    const __half* Bbase = Bt + (size_t)bcol * GBM * K;

    float acc[4][4][4];
    #pragma unroll
    for (int i = 0; i < 4; i++)
        #pragma unroll
        for (int j = 0; j < 4; j++)
            #pragma unroll
            for (int r = 0; r < 4; r++) acc[i][j][r] = 0.0f;

    auto load_tile = [&](int it, int stage) {
        const int koff = it * GBK;
        #pragma unroll
        for (int q = 0; q < 4; q++) {
            const int idx = q * 256 + tid;   // 0..1023
            const int row = idx >> 3;        // 0..127
            const int c8  = idx & 7;
            const int ds  = stage * GSTG + row * GPIT + c8 * 2;
            cp_async16(smem_u32(As64 + ds),
                       Abase + (size_t)row * K + koff + c8 * 8);
            cp_async16(smem_u32(Bs64 + ds),
                       Bbase + (size_t)row * K + koff + c8 * 8);
        }
    };

    const int nit = K / GBK;
    load_tile(0, 0);
    cp_commit();

    for (int it = 0; it < nit; ++it) {
        if (it + 1 < nit) {
            load_tile(it + 1, (it + 1) & 1);
            cp_commit();
            cp_wait1();
        } else {
            cp_wait0();
        }
        __syncthreads();

        const uint2* As_ = As64 + (it & 1) * GSTG;
        const uint2* Bs_ = Bs64 + (it & 1) * GSTG;
        #pragma unroll
        for (int kk = 0; kk < 4; kk++) {
            uint32_t a[4][4];
            uint32_t b[4][2];
            #pragma unroll
            for (int i = 0; i < 4; i++) {
                const int r = warp_m * 64 + i * 16 + gid;
                const uint2 a02 = As_[r * GPIT + kk * 4 + tig];
                const uint2 a13 = As_[(r + 8) * GPIT + kk * 4 + tig];
                a[i][0] = a02.x; a[i][1] = a13.x;
                a[i][2] = a02.y; a[i][3] = a13.y;
            }
            #pragma unroll
            for (int j = 0; j < 4; j++) {
                const int rn = warp_n * 32 + j * 8 + gid;
                const uint2 bb = Bs_[rn * GPIT + kk * 4 + tig];
                b[j][0] = bb.x; b[j][1] = bb.y;
            }
            #pragma unroll
            for (int i = 0; i < 4; i++)
                #pragma unroll
                for (int j = 0; j < 4; j++)
                    mma_f16(acc[i][j], a[i], b[j][0], b[j][1]);
        }
        __syncthreads();
    }

    if (!qkv_mode) {
        #pragma unroll
        for (int i = 0; i < 4; i++) {
            const int row0 = brow * GBM + warp_m * 64 + i * 16 + gid;
            #pragma unroll
            for (int j = 0; j < 4; j++) {
                const int col = bcol * GBM + warp_n * 32 + j * 8 + 2 * tig;
                const float bx = bias[col], by = bias[col + 1];
                float2 v0 = make_float2(acc[i][j][0] + bx, acc[i][j][1] + by);
                float2 v1 = make_float2(acc[i][j][2] + bx, acc[i][j][3] + by);
                *(float2*)(C + (size_t)row0 * N + col) = v0;
                *(float2*)(C + (size_t)(row0 + 8) * N + col) = v1;
            }
        }
        return;
    }

    // qkv mode: section uniform per CTA (8 bcol blocks per 1024-col section)
    const int sec = bcol >> 3;
    #pragma unroll
    for (int i = 0; i < 4; i++) {
        const int t0 = brow * GBM + warp_m * 64 + i * 16 + gid;
        #pragma unroll
        for (int j = 0; j < 4; j++) {
            const int c = bcol * GBM + warp_n * 32 + j * 8 + 2 * tig;
            const float bx = bias[c], by = bias[c + 1];
            const float a0 = acc[i][j][0] + bx, a1 = acc[i][j][1] + by;
            const float a2 = acc[i][j][2] + bx, a3 = acc[i][j][3] + by;
            const int cc = c & (CC - 1);
            const int h = cc >> 6, d = cc & 63;
            const int u = d >> 1;   // 0..31
            const int slot = ((u >> 3) << 3) + ((u & 3) << 1) + ((u & 7) >> 2);

            if (sec == 0) {
                // Q: fp16 pair-packed, prescaled into exp2 domain
                const size_t r0o = (size_t)t0 * (CC / 2) + h * 32 + slot;
                const size_t r1o = (size_t)(t0 + 8) * (CC / 2) + h * 32 + slot;
                Cq[r0o] = pack_f16x2(a0 * SCALE_EXP2, a1 * SCALE_EXP2);
                Cq[r1o] = pack_f16x2(a2 * SCALE_EXP2, a3 * SCALE_EXP2);
            } else if (sec == 1) {
                // K: fp16 pair-packed
                const size_t r0o = (size_t)t0 * (CC / 2) + h * 32 + slot;
                const size_t r1o = (size_t)(t0 + 8) * (CC / 2) + h * 32 + slot;
                Ck[r0o] = pack_f16x2(a0, a1);
                Ck[r1o] = pack_f16x2(a2, a3);
            } else {
                // V: fp16, [b,tile,h][d][tk_perm]
                #pragma unroll
                for (int rr = 0; rr < 2; rr++) {
                    const int t = t0 + rr * 8;
                    const int b_ = t >> 11, tl = t & (TT - 1);
                    const int tile = tl >> 6, tk = tl & 63;
                    const int wv = tk >> 1, hf = tk & 1;
                    const int vs = ((wv >> 3) << 3) + ((wv & 3) << 1) + ((wv & 7) >> 2);
                    const int pos = 2 * vs + hf;
                    __half* vb = Cv + ((((size_t)b_ * (TT / 64) + tile) * HH + h) << 12);
                    const float va = rr ? a2 : a0;
                    const float vc = rr ? a3 : a1;
                    vb[d * 64 + pos]       = __float2half_rn(va);
                    vb[(d + 1) * 64 + pos] = __float2half_rn(vc);
                }
            }
        }
    }
}

// ---------------------------------------------------------------------------
// Flash attention: plain fp16 S + fp16 k16 PV.
// smem (u64 units): stage = K 64x20 + VT 64x20 = 2560; Q = 128x20 = 2560.
// Total: 2 stages + Q = 7680 u64 = 61,440 B.
// ---------------------------------------------------------------------------
#define KP64 20
#define STAGE_U64 (2 * 64 * KP64)         // 2560 u64 = 20,480 B
#define ATTN_SMEM ((2 * STAGE_U64 + 128 * KP64) * 8)   // 61,440 B

__global__ __launch_bounds__(256, 2)
void attn_hyb_kernel(const uint32_t* __restrict__ gq,
                     const uint32_t* __restrict__ gk,
                     const __half* __restrict__ gv,
                     __half* __restrict__ out)
{
    extern __shared__ __align__(16) char asm_raw[];
    uint2* smu  = (uint2*)asm_raw;
    uint2* qbuf = smu + 2 * STAGE_U64;

    const int qb = (int)gridDim.x - 1 - (int)blockIdx.x;
    const int h  = blockIdx.y;
    const int b  = blockIdx.z;
    const int q0 = qb * 128;
    const size_t bT = (size_t)b * TT;

    const int tid  = threadIdx.x;
    const int w    = tid >> 5;
    const int lane = tid & 31;
    const int gid  = lane >> 2;
    const int tig  = lane & 3;

    const int ntiles = 2 * (qb + 1);

    // Tile loader: pure cp.async, 4 x 16B per thread
    auto load_tile = [&](int t, int stage) {
        uint2* base = smu + (size_t)stage * STAGE_U64;
        const size_t kro = (bT + (size_t)t * 64) * (CC / 2) + h * 32;
        const __half* vb = gv + ((((size_t)b * (TT / 64) + t) * HH + h) << 12);
        #pragma unroll
        for (int q = 0; q < 2; q++) {
            const int idx = q * 256 + tid;       // 0..511
            const int row = idx >> 3;            // 0..63
            const int c8  = idx & 7;
            cp_async16(smem_u32(base + row * KP64 + c8 * 2),
                       gk + kro + (size_t)row * (CC / 2) + c8 * 4);
            cp_async16(smem_u32(base + 64 * KP64 + row * KP64 + c8 * 2),
                       vb + row * 64 + c8 * 8);
        }
    };

    // Prologue: Q copy (group 0), tile-0 prefetch (group 1).
    {
        const size_t qro = (bT + q0) * (CC / 2) + h * 32;
        #pragma unroll
        for (int q = 0; q < 4; q++) {
            const int idx = q * 256 + tid;       // 0..1023
            const int row = idx >> 3;            // 0..127
            const int c8  = idx & 7;             // 8 x 16B per 128B row
            cp_async16(smem_u32(qbuf + row * KP64 + c8 * 2),
                       gq + qro + (size_t)row * (CC / 2) + c8 * 4);
        }
    }
    cp_commit();
    load_tile(0, 0);
    cp_commit();

    cp_wait1();          // Q done (tile 0 may still be in flight)
    __syncthreads();

    // Extract Q fp16 A-fragments (already prescaled + permuted)
    const int r0l = w * 16 + gid;
    const int r0g = q0 + r0l;
    uint32_t qf[4][4];
    #pragma unroll
    for (int ks = 0; ks < 4; ks++) {
        const uint2 a02 = qbuf[r0l * KP64 + ks * 4 + tig];
        const uint2 a13 = qbuf[(r0l + 8) * KP64 + ks * 4 + tig];
        qf[ks][0] = a02.x; qf[ks][1] = a13.x;
        qf[ks][2] = a02.y; qf[ks][3] = a13.y;
    }

    float O[8][4];
    #pragma unroll
    for (int j = 0; j < 8; j++)
        #pragma unroll
        for (int r = 0; r < 4; r++) O[j][r] = 0.0f;
    float m0 = -1e30f, m1 = -1e30f, l0 = 0.0f, l1 = 0.0f;

    for (int t = 0; t < ntiles; t++) {
        if (t + 1 < ntiles) {
            load_tile(t + 1, (t + 1) & 1);
            cp_commit();
            cp_wait1();
        } else {
            cp_wait0();
        }
        __syncthreads();

        const uint2* KK2 = smu + (size_t)(t & 1) * STAGE_U64;
        const uint2* VT2 = KK2 + 64 * KP64;
        const int kv0 = t * 64;

        // S = Q @ K^T (plain fp16)
        float s[8][4];
        #pragma unroll
        for (int j = 0; j < 8; j++)
            #pragma unroll
            for (int r = 0; r < 4; r++) s[j][r] = 0.0f;

        #pragma unroll
        for (int ks = 0; ks < 4; ks++) {
            #pragma unroll
            for (int j = 0; j < 8; j++) {
                const uint2 bh = KK2[(j * 8 + gid) * KP64 + ks * 4 + tig];
                mma_f16(s[j], qf[ks], bh.x, bh.y);
            }
        }

        // Causal mask on the two diagonal-straddling tiles
        if (t + 2 >= ntiles) {
            #pragma unroll
            for (int j = 0; j < 8; j++) {
                const int col = kv0 + j * 8 + 2 * tig;
                if (col     > r0g)     s[j][0] = -1e30f;
                if (col + 1 > r0g)     s[j][1] = -1e30f;
                if (col     > r0g + 8) s[j][2] = -1e30f;
                if (col + 1 > r0g + 8) s[j][3] = -1e30f;
            }
        }

        // Online softmax (exp2 domain)
        float mt0 = s[0][0], mt1 = s[0][2];
        #pragma unroll
        for (int j = 0; j < 8; j++) {
            mt0 = fmaxf(mt0, fmaxf(s[j][0], s[j][1]));
            mt1 = fmaxf(mt1, fmaxf(s[j][2], s[j][3]));
        }
        mt0 = fmaxf(mt0, __shfl_xor_sync(0xffffffffu, mt0, 1));
        mt0 = fmaxf(mt0, __shfl_xor_sync(0xffffffffu, mt0, 2));
        mt1 = fmaxf(mt1, __shfl_xor_sync(0xffffffffu, mt1, 1));
        mt1 = fmaxf(mt1, __shfl_xor_sync(0xffffffffu, mt1, 2));

        const float mn0 = fmaxf(m0, mt0), mn1 = fmaxf(m1, mt1);
        const float c0 = ex2(m0 - mn0), c1 = ex2(m1 - mn1);
        l0 *= c0; l1 *= c1;
        #pragma unroll
        for (int j = 0; j < 8; j++) {
            O[j][0] *= c0; O[j][1] *= c0;
            O[j][2] *= c1; O[j][3] *= c1;
        }
        m0 = mn0; m1 = mn1;

        #pragma unroll
        for (int j = 0; j < 8; j++) {
            s[j][0] = ex2(s[j][0] - mn0);
            s[j][1] = ex2(s[j][1] - mn0);
            s[j][2] = ex2(s[j][2] - mn1);
            s[j][3] = ex2(s[j][3] - mn1);
            l0 += s[j][0] + s[j][1];
            l1 += s[j][2] + s[j][3];
        }

        // PV: fp16 k16, P packs directly into A-fragments
        #pragma unroll
        for (int jk = 0; jk < 4; jk++) {
            uint32_t a[4];
            a[0] = pack_f16x2(s[2 * jk][0],     s[2 * jk][1]);
            a[1] = pack_f16x2(s[2 * jk][2],     s[2 * jk][3]);
            a[2] = pack_f16x2(s[2 * jk + 1][0], s[2 * jk + 1][1]);
            a[3] = pack_f16x2(s[2 * jk + 1][2], s[2 * jk + 1][3]);
            #pragma unroll
            for (int jo = 0; jo < 8; jo++) {
                const uint2 vv = VT2[(jo * 8 + gid) * KP64 + jk * 4 + tig];
                mma_f16(O[jo], a, vv.x, vv.y);
            }
        }
        __syncthreads();
    }

    // Finalize: write fp16 pair-pack-permuted rows into g_att16
    l0 += __shfl_xor_sync(0xffffffffu, l0, 1);
    l0 += __shfl_xor_sync(0xffffffffu, l0, 2);
    l1 += __shfl_xor_sync(0xffffffffu, l1, 1);
    l1 += __shfl_xor_sync(0xffffffffu, l1, 2);
    const float i0 = 1.0f / l0, i1 = 1.0f / l1;

    __half* ob = out + (bT + r0g) * CC + h * DD;
    #pragma unroll
    for (int j = 0; j < 8; j++) {
        const int off = ((j >> 1) << 4) + ((2 * tig + (j & 1)) << 1);
        *(uint32_t*)(ob + off) =
            pack_f16x2(O[j][0] * i0, O[j][1] * i0);
        *(uint32_t*)(ob + (size_t)8 * CC + off) =
            pack_f16x2(O[j][2] * i1, O[j][3] * i1);
    }
}

// ---------------------------------------------------------------------------
// Launch
// ---------------------------------------------------------------------------
extern "C" void kernel_launch(void* const* d_in, const int* in_sizes, int n_in,
                              void* d_out, int out_size)
{
    const float* x     = (const float*)d_in[0];
    const float* w_qkv = (const float*)d_in[1];
    const float* b_qkv = (const float*)d_in[2];
    const float* w_out = (const float*)d_in[3];
    const float* b_out = (const float*)d_in[4];
    float* out = (float*)d_out;

    uint32_t* gq = nullptr;    cudaGetSymbolAddress((void**)&gq, g_q16);
    uint32_t* gk = nullptr;    cudaGetSymbolAddress((void**)&gk, g_k16);
    __half*   gv = nullptr;    cudaGetSymbolAddress((void**)&gv, g_v16);
    __half*   att16 = nullptr; cudaGetSymbolAddress((void**)&att16, g_att16);
    __half*   x16 = nullptr;   cudaGetSymbolAddress((void**)&x16, g_x16);
    __half*   wqkvT = nullptr; cudaGetSymbolAddress((void**)&wqkvT, g_wqkvT16);
    __half*   woutT = nullptr; cudaGetSymbolAddress((void**)&woutT, g_woutT16);

    cudaFuncSetAttribute(gemm_f16_kernel,
                         cudaFuncAttributeMaxDynamicSharedMemorySize, GEMM_SMEM);
    cudaFuncSetAttribute(attn_hyb_kernel,
                         cudaFuncAttributeMaxDynamicSharedMemorySize, ATTN_SMEM);

    // Preproc: x -> fp16 perm; weights -> transposed fp16 perm
    {
        const int ngroups = MM * CC / 16;
        f16perm_convert_kernel<<<ngroups / 256, 256>>>(x, x16, ngroups);
        dim3 blk(32, 8);
        transpose_f16perm_kernel<<<dim3((3 * CC) / 32, CC / 32), blk>>>(w_qkv, wqkvT, CC, 3 * CC);
        transpose_f16perm_kernel<<<dim3(CC / 32, CC / 32), blk>>>(w_out, woutT, CC, CC);
    }

    // QKV projection (fp16 mma, BK=64) with fused Q/K/V transformation
    {
        dim3 grid((3 * CC) / 128, MM / 128);
        gemm_f16_kernel<<<grid, 256, GEMM_SMEM>>>(x16, wqkvT, b_qkv, nullptr,
                                                  MM, 3 * CC, CC, 1,
                                                  gq, gk, gv);
    }

    // Flash attention (plain fp16 S / fp16 PV)
    {
        dim3 grid(TT / 128, HH, BB);
        attn_hyb_kernel<<<grid, 256, ATTN_SMEM>>>(gq, gk, gv, att16);
    }

    // Output projection (fp16 mma, BK=64, plain epilogue)
    {
        dim3 grid(CC / 128, MM / 128);
        gemm_f16_kernel<<<grid, 256, GEMM_SMEM>>>(att16, woutT, b_out, out,
                                                  MM, CC, CC, 0,
                                                  nullptr, nullptr, nullptr);
    }
}